// round 1
// baseline (speedup 1.0000x reference)
#include <cuda_runtime.h>
#include <math.h>

// Problem constants
#define BB 64
#define NN 128
#define DLAT 80
#define NH 8
#define DH 64
#define INNER 512
#define FFD 160
#define MHD 20
#define DEPTH 24
#define ROWS (BB * NN)   // 8192

// ---------------------------------------------------------------------------
// Scratch (device globals; no allocation allowed)
// ---------------------------------------------------------------------------
__device__ float g_x[ROWS * DLAT];          // residual stream
__device__ float g_h[ROWS * DLAT];          // LN output
__device__ float g_q[ROWS * INNER];         // Q
__device__ float g_kv[ROWS * 2 * INNER];    // K|V
__device__ float g_o[ROWS * INNER];         // attention output
__device__ float g_f[ROWS * FFD];           // FF hidden
__device__ float g_bias[BB * NN * NN];      // graph attention bias

// ---------------------------------------------------------------------------
// Graph bias: bias[b,i,j] = sum_h mean_f(edge_emb[ei[b,i,j,h,f]]) * w[h] / sp
//                           + spatial_emb[spatial_pos[b,i,j]]
// ---------------------------------------------------------------------------
__global__ void bias_kernel(const int* __restrict__ spatial_pos,
                            const int* __restrict__ edge_input,
                            const float* __restrict__ edge_emb,
                            const float* __restrict__ edge_dis_w,
                            const float* __restrict__ spatial_emb,
                            float* __restrict__ bias)
{
    __shared__ float s_edge[64];
    __shared__ float s_w[MHD];
    __shared__ float s_sp[40];
    int t = threadIdx.x;               // 128 threads
    if (t < 64) s_edge[t] = edge_emb[t];
    if (t < MHD) s_w[t] = edge_dis_w[t];
    if (t >= 64 && t < 104) s_sp[t - 64] = spatial_emb[t - 64];
    __syncthreads();

    long bi = blockIdx.x;              // b*N + i
    int j = t;
    const int* ei = edge_input + (bi * NN + j) * (MHD * 3);
    float acc = 0.f;
#pragma unroll
    for (int hh = 0; hh < MHD; hh++) {
        float e = (s_edge[ei[hh * 3 + 0]] + s_edge[ei[hh * 3 + 1]] +
                   s_edge[ei[hh * 3 + 2]]) * (1.f / 3.f);
        acc += e * s_w[hh];
    }
    int sp0 = spatial_pos[bi * NN + j];
    int sp = (sp0 == 0) ? 1 : sp0;
    sp = (sp > 1) ? sp - 1 : sp;
    sp = min(sp, MHD);
    bias[bi * NN + j] = acc / (float)sp + s_sp[sp0];
}

// ---------------------------------------------------------------------------
// Node embedding: x = atom_emb[x_nodes] + indeg_emb[indeg] + outdeg_emb[outdeg]
// ---------------------------------------------------------------------------
__global__ void embed_kernel(const int* __restrict__ x_nodes,
                             const int* __restrict__ indeg,
                             const int* __restrict__ outdeg,
                             const float* __restrict__ atom_emb,
                             const float* __restrict__ indeg_emb,
                             const float* __restrict__ outdeg_emb,
                             float* __restrict__ x)
{
    int r = blockIdx.x;      // 8192 rows
    int d = threadIdx.x;     // 80
    int a = x_nodes[r], i = indeg[r], o = outdeg[r];
    x[(long)r * DLAT + d] = atom_emb[a * DLAT + d] + indeg_emb[i * DLAT + d]
                          + outdeg_emb[o * DLAT + d];
}

// ---------------------------------------------------------------------------
// LayerNorm: one warp per 80-dim row (lanes cover d, d+32, d+64)
// ---------------------------------------------------------------------------
__global__ void ln_kernel(const float* __restrict__ x, const float* __restrict__ g,
                          const float* __restrict__ b, float* __restrict__ h)
{
    int w = (blockIdx.x * blockDim.x + threadIdx.x) >> 5;
    int lane = threadIdx.x & 31;
    if (w >= ROWS) return;
    const float* xr = x + (long)w * DLAT;
    float v0 = xr[lane];
    float v1 = xr[lane + 32];
    float v2 = (lane + 64 < DLAT) ? xr[lane + 64] : 0.f;
    float s = v0 + v1 + v2;
#pragma unroll
    for (int o = 16; o; o >>= 1) s += __shfl_xor_sync(0xffffffffu, s, o);
    float mean = s * (1.f / DLAT);
    float d0 = v0 - mean, d1 = v1 - mean;
    float d2 = (lane + 64 < DLAT) ? (v2 - mean) : 0.f;
    float vs = d0 * d0 + d1 * d1 + d2 * d2;
#pragma unroll
    for (int o = 16; o; o >>= 1) vs += __shfl_xor_sync(0xffffffffu, vs, o);
    float inv = rsqrtf(vs * (1.f / DLAT) + 1e-5f);
    float* hr = h + (long)w * DLAT;
    hr[lane]      = d0 * inv * g[lane] + b[lane];
    hr[lane + 32] = d1 * inv * g[lane + 32] + b[lane + 32];
    if (lane + 64 < DLAT)
        hr[lane + 64] = d2 * inv * g[lane + 64] + b[lane + 64];
}

// ---------------------------------------------------------------------------
// fp32 tiled GEMM: C[M,Nc] = A[M,K] @ W[K,Nc] (+ epilogue)
//   EPI 0: plain store
//   EPI 1: + bias[n] + res[m,n]  (residual add; safe in-place with C == res)
//   EPI 2: gelu_exact(acc + bias[n])
// BM=BN=64, BK=16, 256 threads, 4x4 per-thread tile.
// ---------------------------------------------------------------------------
#define BM 64
#define BN 64
#define BK 16
#define AST (BM + 4)   // 68: float4-aligned, low-conflict
#define BST (BN + 4)

template <int EPI>
__global__ void __launch_bounds__(256) gemm_kernel(
    const float* __restrict__ A, const float* __restrict__ W,
    const float* __restrict__ bias, const float* __restrict__ res,
    float* __restrict__ C, int M, int K, int Nc)
{
    __shared__ float As[BK * AST];
    __shared__ float Bs[BK * BST];
    int bm = blockIdx.y * BM;
    int bn = blockIdx.x * BN;
    int tid = threadIdx.x;
    int tx = tid & 15, ty = tid >> 4;
    float acc[4][4] = {};

    for (int k0 = 0; k0 < K; k0 += BK) {
        {   // A tile: 64 rows x 16 k, float4 per thread, stored transposed
            int m = tid >> 2;
            int kq = (tid & 3) * 4;
            float4 a4 = *(const float4*)(A + (long)(bm + m) * K + k0 + kq);
            As[(kq + 0) * AST + m] = a4.x;
            As[(kq + 1) * AST + m] = a4.y;
            As[(kq + 2) * AST + m] = a4.z;
            As[(kq + 3) * AST + m] = a4.w;
        }
        {   // B tile: 16 k x 64 n, guarded for Nc not multiple of 64
            int k = tid >> 4;
            int nq = (tid & 15) * 4;
            int n = bn + nq;
            float4 b4 = make_float4(0.f, 0.f, 0.f, 0.f);
            const float* wp = W + (long)(k0 + k) * Nc;
            if (n + 3 < Nc) {
                b4 = *(const float4*)(wp + n);
            } else if (n < Nc) {
                b4.x = wp[n];
                if (n + 1 < Nc) b4.y = wp[n + 1];
                if (n + 2 < Nc) b4.z = wp[n + 2];
            }
            *(float4*)&Bs[k * BST + nq] = b4;
        }
        __syncthreads();
#pragma unroll
        for (int kk = 0; kk < BK; kk++) {
            float4 a4 = *(const float4*)&As[kk * AST + ty * 4];
            float4 b4 = *(const float4*)&Bs[kk * BST + tx * 4];
            float a[4] = {a4.x, a4.y, a4.z, a4.w};
            float bb[4] = {b4.x, b4.y, b4.z, b4.w};
#pragma unroll
            for (int i = 0; i < 4; i++)
#pragma unroll
                for (int j = 0; j < 4; j++)
                    acc[i][j] += a[i] * bb[j];
        }
        __syncthreads();
    }

#pragma unroll
    for (int i = 0; i < 4; i++) {
        int m = bm + ty * 4 + i;
#pragma unroll
        for (int j = 0; j < 4; j++) {
            int n = bn + tx * 4 + j;
            if (n >= Nc) continue;
            float v = acc[i][j];
            if (EPI == 1) v += bias[n] + res[(long)m * Nc + n];
            if (EPI == 2) {
                v += bias[n];
                v = 0.5f * v * (1.f + erff(v * 0.70710678118654752f));
            }
            C[(long)m * Nc + n] = v;
        }
    }
}

// ---------------------------------------------------------------------------
// Fused attention: one block per (b, h), 128 threads (thread = query row i).
// K/V tiles + score rows in dynamic SMEM; q row + output accum in registers.
// ---------------------------------------------------------------------------
#define KST 68                              // DH + 4, float4-aligned
#define ATTN_SMEM ((2 * NN * KST + NN * 129) * 4)

__global__ void __launch_bounds__(128) attn_kernel(
    const float* __restrict__ q, const float* __restrict__ kv,
    const float* __restrict__ bias, float* __restrict__ o)
{
    extern __shared__ float sm[];
    float* Ks = sm;                  // [128][KST]
    float* Vs = sm + NN * KST;       // [128][KST]
    float* Ss = sm + 2 * NN * KST;   // [128][129]

    int bh = blockIdx.x;
    int b = bh >> 3, h = bh & 7;
    int t = threadIdx.x;             // row index i, 0..127

    // Load K and V rows (row t of this (b,h) slice)
    const float* kr = kv + ((long)(b * NN + t)) * (2 * INNER) + h * DH;
    const float* vr = kr + INNER;
#pragma unroll
    for (int i = 0; i < DH / 4; i++) {
        *(float4*)&Ks[t * KST + 4 * i] = *(const float4*)&kr[4 * i];
        *(float4*)&Vs[t * KST + 4 * i] = *(const float4*)&vr[4 * i];
    }
    __syncthreads();

    // Pass 1: scores + row max
    float qreg[DH];
    const float* qr = q + ((long)(b * NN + t)) * INNER + h * DH;
#pragma unroll
    for (int i = 0; i < DH / 4; i++)
        *(float4*)&qreg[4 * i] = *(const float4*)&qr[4 * i];

    const float* brow = bias + ((long)b * NN + t) * NN;
    float mx = -1e30f;
    for (int j = 0; j < NN; j++) {
        float s0 = 0.f, s1 = 0.f, s2 = 0.f, s3 = 0.f;
#pragma unroll
        for (int d = 0; d < DH; d += 4) {
            float4 k4 = *(const float4*)&Ks[j * KST + d];
            s0 += qreg[d]     * k4.x;
            s1 += qreg[d + 1] * k4.y;
            s2 += qreg[d + 2] * k4.z;
            s3 += qreg[d + 3] * k4.w;
        }
        float s = ((s0 + s1) + (s2 + s3)) * 0.125f + brow[j];
        Ss[t * 129 + j] = s;
        mx = fmaxf(mx, s);
    }

    // Pass 2: softmax-weighted sum of V
    float acc[DH];
#pragma unroll
    for (int d = 0; d < DH; d++) acc[d] = 0.f;
    float sum = 0.f;
    for (int j = 0; j < NN; j++) {
        float p = expf(Ss[t * 129 + j] - mx);
        sum += p;
#pragma unroll
        for (int d = 0; d < DH; d += 4) {
            float4 v4 = *(const float4*)&Vs[j * KST + d];
            acc[d]     += p * v4.x;
            acc[d + 1] += p * v4.y;
            acc[d + 2] += p * v4.z;
            acc[d + 3] += p * v4.w;
        }
    }
    float inv = 1.f / sum;
    float* orow = o + ((long)(b * NN + t)) * INNER + h * DH;
#pragma unroll
    for (int d = 0; d < DH; d += 4) {
        float4 r;
        r.x = acc[d] * inv; r.y = acc[d + 1] * inv;
        r.z = acc[d + 2] * inv; r.w = acc[d + 3] * inv;
        *(float4*)&orow[d] = r;
    }
}

// ---------------------------------------------------------------------------
// Head: mean-pool over N, LayerNorm, dot with Wf
// ---------------------------------------------------------------------------
__global__ void head_kernel(const float* __restrict__ x, const float* __restrict__ g,
                            const float* __restrict__ be, const float* __restrict__ Wf,
                            const float* __restrict__ bf, float* __restrict__ out)
{
    __shared__ float pool[DLAT];
    int b = blockIdx.x;
    int t = threadIdx.x;     // 128 threads
    if (t < DLAT) {
        float s = 0.f;
        const float* xb = x + (long)b * NN * DLAT + t;
        for (int n = 0; n < NN; n++) s += xb[n * DLAT];
        pool[t] = s * (1.f / NN);
    }
    __syncthreads();
    if (t < 32) {
        float v0 = pool[t], v1 = pool[t + 32];
        float v2 = (t + 64 < DLAT) ? pool[t + 64] : 0.f;
        float s = v0 + v1 + v2;
#pragma unroll
        for (int o = 16; o; o >>= 1) s += __shfl_xor_sync(0xffffffffu, s, o);
        float mean = s * (1.f / DLAT);
        float d0 = v0 - mean, d1 = v1 - mean;
        float d2 = (t + 64 < DLAT) ? (v2 - mean) : 0.f;
        float vs = d0 * d0 + d1 * d1 + d2 * d2;
#pragma unroll
        for (int o = 16; o; o >>= 1) vs += __shfl_xor_sync(0xffffffffu, vs, o);
        float inv = rsqrtf(vs * (1.f / DLAT) + 1e-5f);
        float dot = (d0 * inv * g[t] + be[t]) * Wf[t]
                  + (d1 * inv * g[t + 32] + be[t + 32]) * Wf[t + 32];
        if (t + 64 < DLAT)
            dot += (d2 * inv * g[t + 64] + be[t + 64]) * Wf[t + 64];
#pragma unroll
        for (int o = 16; o; o >>= 1) dot += __shfl_xor_sync(0xffffffffu, dot, o);
        if (t == 0) out[b] = dot + bf[0];
    }
}

// ---------------------------------------------------------------------------
// Launch
// ---------------------------------------------------------------------------
extern "C" void kernel_launch(void* const* d_in, const int* in_sizes, int n_in,
                              void* d_out, int out_size)
{
    const int*   spatial_pos = (const int*)d_in[0];
    const int*   edge_input  = (const int*)d_in[1];
    const int*   x_nodes     = (const int*)d_in[2];
    const int*   indeg       = (const int*)d_in[3];
    const int*   outdeg      = (const int*)d_in[4];
    const float* atom_emb    = (const float*)d_in[5];
    const float* indeg_emb   = (const float*)d_in[6];
    const float* outdeg_emb  = (const float*)d_in[7];
    const float* edge_emb    = (const float*)d_in[8];
    const float* edge_dis_w  = (const float*)d_in[9];
    const float* spatial_emb = (const float*)d_in[10];
    const float* ln1_g = (const float*)d_in[11];
    const float* ln1_b = (const float*)d_in[12];
    const float* Wq    = (const float*)d_in[13];
    const float* Wkv   = (const float*)d_in[14];
    const float* Wo    = (const float*)d_in[15];
    const float* bo    = (const float*)d_in[16];
    const float* ln2_g = (const float*)d_in[17];
    const float* ln2_b = (const float*)d_in[18];
    const float* W1    = (const float*)d_in[19];
    const float* b1    = (const float*)d_in[20];
    const float* W2    = (const float*)d_in[21];
    const float* b2    = (const float*)d_in[22];
    const float* lnf_g = (const float*)d_in[23];
    const float* lnf_b = (const float*)d_in[24];
    const float* Wf    = (const float*)d_in[25];
    const float* bf    = (const float*)d_in[26];
    float* out = (float*)d_out;

    float *gx, *gh, *gq, *gkv, *go, *gf, *gb;
    cudaGetSymbolAddress((void**)&gx,  g_x);
    cudaGetSymbolAddress((void**)&gh,  g_h);
    cudaGetSymbolAddress((void**)&gq,  g_q);
    cudaGetSymbolAddress((void**)&gkv, g_kv);
    cudaGetSymbolAddress((void**)&go,  g_o);
    cudaGetSymbolAddress((void**)&gf,  g_f);
    cudaGetSymbolAddress((void**)&gb,  g_bias);

    cudaFuncSetAttribute(attn_kernel,
                         cudaFuncAttributeMaxDynamicSharedMemorySize, ATTN_SMEM);

    bias_kernel<<<BB * NN, 128>>>(spatial_pos, edge_input, edge_emb,
                                  edge_dis_w, spatial_emb, gb);
    embed_kernel<<<ROWS, DLAT>>>(x_nodes, indeg, outdeg,
                                 atom_emb, indeg_emb, outdeg_emb, gx);

    for (int l = 0; l < DEPTH; l++) {
        ln_kernel<<<ROWS / 8, 256>>>(gx, ln1_g + l * DLAT, ln1_b + l * DLAT, gh);
        gemm_kernel<0><<<dim3(INNER / BN, ROWS / BM), 256>>>(
            gh, Wq + (long)l * DLAT * INNER, nullptr, nullptr,
            gq, ROWS, DLAT, INNER);
        gemm_kernel<0><<<dim3(2 * INNER / BN, ROWS / BM), 256>>>(
            gh, Wkv + (long)l * DLAT * 2 * INNER, nullptr, nullptr,
            gkv, ROWS, DLAT, 2 * INNER);
        attn_kernel<<<BB * NH, 128, ATTN_SMEM>>>(gq, gkv, gb, go);
        gemm_kernel<1><<<dim3(2, ROWS / BM), 256>>>(
            go, Wo + (long)l * INNER * DLAT, bo + l * DLAT, gx,
            gx, ROWS, INNER, DLAT);
        ln_kernel<<<ROWS / 8, 256>>>(gx, ln2_g + l * DLAT, ln2_b + l * DLAT, gh);
        gemm_kernel<2><<<dim3(3, ROWS / BM), 256>>>(
            gh, W1 + (long)l * DLAT * FFD, b1 + l * FFD, nullptr,
            gf, ROWS, DLAT, FFD);
        gemm_kernel<1><<<dim3(2, ROWS / BM), 256>>>(
            gf, W2 + (long)l * FFD * DLAT, b2 + l * DLAT, gx,
            gx, ROWS, FFD, DLAT);
    }

    head_kernel<<<BB, 128>>>(gx, lnf_g, lnf_b, Wf, bf, out);
}

// round 2
// speedup vs baseline: 1.2905x; 1.2905x over previous
#include <cuda_runtime.h>
#include <math.h>

// Problem constants
#define BB 64
#define NN 128
#define DLAT 80
#define NH 8
#define DH 64
#define INNER 512
#define FFD 160
#define MHD 20
#define DEPTH 24
#define ROWS (BB * NN)   // 8192

// ---------------------------------------------------------------------------
// Scratch (device globals; no allocation allowed)
// ---------------------------------------------------------------------------
__device__ float g_x[ROWS * DLAT];          // residual stream
__device__ float g_h[ROWS * DLAT];          // LN output
__device__ float g_qkv[ROWS * 3 * INNER];   // fused Q|K|V (row stride 1536)
__device__ float g_o[ROWS * INNER];         // attention output
__device__ float g_f[ROWS * FFD];           // FF hidden
__device__ float g_bias[BB * NN * NN];      // graph attention bias

// ---------------------------------------------------------------------------
// Graph bias
// ---------------------------------------------------------------------------
__global__ void bias_kernel(const int* __restrict__ spatial_pos,
                            const int* __restrict__ edge_input,
                            const float* __restrict__ edge_emb,
                            const float* __restrict__ edge_dis_w,
                            const float* __restrict__ spatial_emb,
                            float* __restrict__ bias)
{
    __shared__ float s_edge[64];
    __shared__ float s_w[MHD];
    __shared__ float s_sp[40];
    int t = threadIdx.x;               // 128 threads
    if (t < 64) s_edge[t] = edge_emb[t];
    if (t < MHD) s_w[t] = edge_dis_w[t];
    if (t >= 64 && t < 104) s_sp[t - 64] = spatial_emb[t - 64];
    __syncthreads();

    long bi = blockIdx.x;              // b*N + i
    int j = t;
    const int* ei = edge_input + (bi * NN + j) * (MHD * 3);
    float acc = 0.f;
#pragma unroll
    for (int hh = 0; hh < MHD; hh++) {
        float e = (s_edge[ei[hh * 3 + 0]] + s_edge[ei[hh * 3 + 1]] +
                   s_edge[ei[hh * 3 + 2]]) * (1.f / 3.f);
        acc += e * s_w[hh];
    }
    int sp0 = spatial_pos[bi * NN + j];
    int sp = (sp0 == 0) ? 1 : sp0;
    sp = (sp > 1) ? sp - 1 : sp;
    sp = min(sp, MHD);
    bias[bi * NN + j] = acc / (float)sp + s_sp[sp0];
}

// ---------------------------------------------------------------------------
// Node embedding
// ---------------------------------------------------------------------------
__global__ void embed_kernel(const int* __restrict__ x_nodes,
                             const int* __restrict__ indeg,
                             const int* __restrict__ outdeg,
                             const float* __restrict__ atom_emb,
                             const float* __restrict__ indeg_emb,
                             const float* __restrict__ outdeg_emb,
                             float* __restrict__ x)
{
    int r = blockIdx.x;      // 8192 rows
    int d = threadIdx.x;     // 80
    int a = x_nodes[r], i = indeg[r], o = outdeg[r];
    x[(long)r * DLAT + d] = atom_emb[a * DLAT + d] + indeg_emb[i * DLAT + d]
                          + outdeg_emb[o * DLAT + d];
}

// ---------------------------------------------------------------------------
// LayerNorm: one warp per 80-dim row
// ---------------------------------------------------------------------------
__global__ void ln_kernel(const float* __restrict__ x, const float* __restrict__ g,
                          const float* __restrict__ b, float* __restrict__ h)
{
    int w = (blockIdx.x * blockDim.x + threadIdx.x) >> 5;
    int lane = threadIdx.x & 31;
    if (w >= ROWS) return;
    const float* xr = x + (long)w * DLAT;
    float v0 = xr[lane];
    float v1 = xr[lane + 32];
    float v2 = (lane + 64 < DLAT) ? xr[lane + 64] : 0.f;
    float s = v0 + v1 + v2;
#pragma unroll
    for (int o = 16; o; o >>= 1) s += __shfl_xor_sync(0xffffffffu, s, o);
    float mean = s * (1.f / DLAT);
    float d0 = v0 - mean, d1 = v1 - mean;
    float d2 = (lane + 64 < DLAT) ? (v2 - mean) : 0.f;
    float vs = d0 * d0 + d1 * d1 + d2 * d2;
#pragma unroll
    for (int o = 16; o; o >>= 1) vs += __shfl_xor_sync(0xffffffffu, vs, o);
    float inv = rsqrtf(vs * (1.f / DLAT) + 1e-5f);
    float* hr = h + (long)w * DLAT;
    hr[lane]      = d0 * inv * g[lane] + b[lane];
    hr[lane + 32] = d1 * inv * g[lane + 32] + b[lane + 32];
    if (lane + 64 < DLAT)
        hr[lane + 64] = d2 * inv * g[lane + 64] + b[lane + 64];
}

// ---------------------------------------------------------------------------
// Wide fp32 GEMM: C[m, coff+n] = A[M,K] @ W[K,Nc], row stride ldc.
// BM=BN=128, BK=16, 256 threads, 8x8 micro-tile (cols tx*4 and 64+tx*4).
// Requires: M%128==0, Nc%128==0, K%16==0. No guards.
// ---------------------------------------------------------------------------
#define WBM 128
#define WBN 128
#define WBK 16
#define WAST 132
#define WBST 132

__global__ void __launch_bounds__(256) gemm_wide_kernel(
    const float* __restrict__ A, const float* __restrict__ W,
    float* __restrict__ C, int M, int K, int Nc, int ldc, int coff)
{
    __shared__ float As[WBK * WAST];
    __shared__ float Bs[WBK * WBST];
    int bm = blockIdx.y * WBM;
    int bn = blockIdx.x * WBN;
    int tid = threadIdx.x;
    int tx = tid & 15, ty = tid >> 4;
    float acc[8][8] = {};

    for (int k0 = 0; k0 < K; k0 += WBK) {
        {   // A tile: 128 rows x 16 k; 2 threads per row, 8 k each
            int m = tid >> 1;
            int kq = (tid & 1) * 8;
            const float* ap = A + (long)(bm + m) * K + k0 + kq;
            float4 a0 = *(const float4*)ap;
            float4 a1 = *(const float4*)(ap + 4);
            As[(kq + 0) * WAST + m] = a0.x;
            As[(kq + 1) * WAST + m] = a0.y;
            As[(kq + 2) * WAST + m] = a0.z;
            As[(kq + 3) * WAST + m] = a0.w;
            As[(kq + 4) * WAST + m] = a1.x;
            As[(kq + 5) * WAST + m] = a1.y;
            As[(kq + 6) * WAST + m] = a1.z;
            As[(kq + 7) * WAST + m] = a1.w;
        }
        {   // B tile: 16 k x 128 n; thread covers 8 n
            int k = tid >> 4;
            int nq = (tid & 15) * 8;
            const float* wp = W + (long)(k0 + k) * Nc + bn + nq;
            *(float4*)&Bs[k * WBST + nq]     = *(const float4*)wp;
            *(float4*)&Bs[k * WBST + nq + 4] = *(const float4*)(wp + 4);
        }
        __syncthreads();
#pragma unroll
        for (int kk = 0; kk < WBK; kk++) {
            float a[8], bv[8];
            *(float4*)&a[0]  = *(const float4*)&As[kk * WAST + ty * 8];
            *(float4*)&a[4]  = *(const float4*)&As[kk * WAST + ty * 8 + 4];
            *(float4*)&bv[0] = *(const float4*)&Bs[kk * WBST + tx * 4];
            *(float4*)&bv[4] = *(const float4*)&Bs[kk * WBST + 64 + tx * 4];
#pragma unroll
            for (int i = 0; i < 8; i++)
#pragma unroll
                for (int j = 0; j < 8; j++)
                    acc[i][j] += a[i] * bv[j];
        }
        __syncthreads();
    }
#pragma unroll
    for (int i = 0; i < 8; i++) {
        long m = bm + ty * 8 + i;
#pragma unroll
        for (int jg = 0; jg < 2; jg++) {
            int n = bn + jg * 64 + tx * 4;
            float4 r;
            r.x = acc[i][jg * 4 + 0];
            r.y = acc[i][jg * 4 + 1];
            r.z = acc[i][jg * 4 + 2];
            r.w = acc[i][jg * 4 + 3];
            *(float4*)&C[m * ldc + coff + n] = r;
        }
    }
}

// ---------------------------------------------------------------------------
// Narrow fp32 GEMM (proven): 64x64 block, 4x4 micro, guards for Nc.
//   EPI 0: plain  EPI 1: +bias[n]+res  EPI 2: gelu(acc+bias[n])
// ---------------------------------------------------------------------------
#define BM 64
#define BN 64
#define BK 16
#define AST (BM + 4)
#define BST (BN + 4)

template <int EPI>
__global__ void __launch_bounds__(256) gemm_kernel(
    const float* __restrict__ A, const float* __restrict__ W,
    const float* __restrict__ bias, const float* __restrict__ res,
    float* __restrict__ C, int M, int K, int Nc)
{
    __shared__ float As[BK * AST];
    __shared__ float Bs[BK * BST];
    int bm = blockIdx.y * BM;
    int bn = blockIdx.x * BN;
    int tid = threadIdx.x;
    int tx = tid & 15, ty = tid >> 4;
    float acc[4][4] = {};

    for (int k0 = 0; k0 < K; k0 += BK) {
        {
            int m = tid >> 2;
            int kq = (tid & 3) * 4;
            float4 a4 = *(const float4*)(A + (long)(bm + m) * K + k0 + kq);
            As[(kq + 0) * AST + m] = a4.x;
            As[(kq + 1) * AST + m] = a4.y;
            As[(kq + 2) * AST + m] = a4.z;
            As[(kq + 3) * AST + m] = a4.w;
        }
        {
            int k = tid >> 4;
            int nq = (tid & 15) * 4;
            int n = bn + nq;
            float4 b4 = make_float4(0.f, 0.f, 0.f, 0.f);
            const float* wp = W + (long)(k0 + k) * Nc;
            if (n + 3 < Nc) {
                b4 = *(const float4*)(wp + n);
            } else if (n < Nc) {
                b4.x = wp[n];
                if (n + 1 < Nc) b4.y = wp[n + 1];
                if (n + 2 < Nc) b4.z = wp[n + 2];
            }
            *(float4*)&Bs[k * BST + nq] = b4;
        }
        __syncthreads();
#pragma unroll
        for (int kk = 0; kk < BK; kk++) {
            float4 a4 = *(const float4*)&As[kk * AST + ty * 4];
            float4 b4 = *(const float4*)&Bs[kk * BST + tx * 4];
            float a[4] = {a4.x, a4.y, a4.z, a4.w};
            float bb[4] = {b4.x, b4.y, b4.z, b4.w};
#pragma unroll
            for (int i = 0; i < 4; i++)
#pragma unroll
                for (int j = 0; j < 4; j++)
                    acc[i][j] += a[i] * bb[j];
        }
        __syncthreads();
    }

#pragma unroll
    for (int i = 0; i < 4; i++) {
        int m = bm + ty * 4 + i;
#pragma unroll
        for (int j = 0; j < 4; j++) {
            int n = bn + tx * 4 + j;
            if (n >= Nc) continue;
            float v = acc[i][j];
            if (EPI == 1) v += bias[n] + res[(long)m * Nc + n];
            if (EPI == 2) {
                v += bias[n];
                v = 0.5f * v * (1.f + erff(v * 0.70710678118654752f));
            }
            C[(long)m * Nc + n] = v;
        }
    }
}

// ---------------------------------------------------------------------------
// Fused attention, one-pass online softmax.
// Block = (b, h), 256 threads: thread pair (2*qi, 2*qi+1) splits DH in halves.
// K/V halves in smem (row stride 72, half offset 36 -> conflict-free).
// ---------------------------------------------------------------------------
#define AKST 72
#define ATTN_SMEM (2 * NN * AKST * 4)   // 73728 bytes

__global__ void __launch_bounds__(256) attn_kernel(
    const float* __restrict__ qkv, const float* __restrict__ bias,
    float* __restrict__ o)
{
    extern __shared__ float sm[];
    float* Ks = sm;
    float* Vs = sm + NN * AKST;

    int bh = blockIdx.x;
    int b = bh >> 3, h = bh & 7;
    int t = threadIdx.x;
    int qi = t >> 1;
    int half = t & 1;
    int doff = half * 32;    // global half offset
    int soff = half * 36;    // smem half offset (bank-shifted)

    // Load K,V halves (K at col 512, V at col 1024 of fused qkv rows)
    const float* kr = qkv + ((long)(b * NN + qi)) * 1536 + 512 + h * DH + doff;
    const float* vr = kr + 512;
    float* ksr = Ks + qi * AKST + soff;
    float* vsr = Vs + qi * AKST + soff;
#pragma unroll
    for (int i = 0; i < 8; i++) {
        *(float4*)&ksr[4 * i] = *(const float4*)&kr[4 * i];
        *(float4*)&vsr[4 * i] = *(const float4*)&vr[4 * i];
    }
    __syncthreads();

    float qreg[32];
    const float* qr = qkv + ((long)(b * NN + qi)) * 1536 + h * DH + doff;
#pragma unroll
    for (int i = 0; i < 8; i++)
        *(float4*)&qreg[4 * i] = *(const float4*)&qr[4 * i];

    const float* brow = bias + ((long)b * NN + qi) * NN;

    float m = -1e30f, sum = 0.f;
    float acc[32];
#pragma unroll
    for (int d = 0; d < 32; d++) acc[d] = 0.f;

    for (int j0 = 0; j0 < NN; j0 += 8) {
        float4 b0 = *(const float4*)&brow[j0];
        float4 b1 = *(const float4*)&brow[j0 + 4];
        float bb[8] = {b0.x, b0.y, b0.z, b0.w, b1.x, b1.y, b1.z, b1.w};
        float s[8];
#pragma unroll
        for (int jj = 0; jj < 8; jj++) {
            const float* kp = Ks + (j0 + jj) * AKST + soff;
            float p0 = 0.f, p1 = 0.f, p2 = 0.f, p3 = 0.f;
#pragma unroll
            for (int d = 0; d < 32; d += 4) {
                float4 k4 = *(const float4*)&kp[d];
                p0 += qreg[d]     * k4.x;
                p1 += qreg[d + 1] * k4.y;
                p2 += qreg[d + 2] * k4.z;
                p3 += qreg[d + 3] * k4.w;
            }
            float part = (p0 + p1) + (p2 + p3);
            part += __shfl_xor_sync(0xffffffffu, part, 1);   // combine halves
            s[jj] = part * 0.125f + bb[jj];
        }
        float cmax = s[0];
#pragma unroll
        for (int jj = 1; jj < 8; jj++) cmax = fmaxf(cmax, s[jj]);
        float mnew = fmaxf(m, cmax);
        float c = __expf(m - mnew);
        m = mnew;
        sum *= c;
#pragma unroll
        for (int d = 0; d < 32; d++) acc[d] *= c;
#pragma unroll
        for (int jj = 0; jj < 8; jj++) {
            float p = __expf(s[jj] - m);
            sum += p;
            const float* vp = Vs + (j0 + jj) * AKST + soff;
#pragma unroll
            for (int d = 0; d < 32; d += 4) {
                float4 v4 = *(const float4*)&vp[d];
                acc[d]     += p * v4.x;
                acc[d + 1] += p * v4.y;
                acc[d + 2] += p * v4.z;
                acc[d + 3] += p * v4.w;
            }
        }
    }
    float inv = 1.f / sum;
    float* orow = o + ((long)(b * NN + qi)) * INNER + h * DH + doff;
#pragma unroll
    for (int d = 0; d < 32; d += 4) {
        float4 r;
        r.x = acc[d] * inv;     r.y = acc[d + 1] * inv;
        r.z = acc[d + 2] * inv; r.w = acc[d + 3] * inv;
        *(float4*)&orow[d] = r;
    }
}

// ---------------------------------------------------------------------------
// Head: mean-pool over N, LayerNorm, dot with Wf
// ---------------------------------------------------------------------------
__global__ void head_kernel(const float* __restrict__ x, const float* __restrict__ g,
                            const float* __restrict__ be, const float* __restrict__ Wf,
                            const float* __restrict__ bf, float* __restrict__ out)
{
    __shared__ float pool[DLAT];
    int b = blockIdx.x;
    int t = threadIdx.x;     // 128 threads
    if (t < DLAT) {
        float s = 0.f;
        const float* xb = x + (long)b * NN * DLAT + t;
        for (int n = 0; n < NN; n++) s += xb[n * DLAT];
        pool[t] = s * (1.f / NN);
    }
    __syncthreads();
    if (t < 32) {
        float v0 = pool[t], v1 = pool[t + 32];
        float v2 = (t + 64 < DLAT) ? pool[t + 64] : 0.f;
        float s = v0 + v1 + v2;
#pragma unroll
        for (int o = 16; o; o >>= 1) s += __shfl_xor_sync(0xffffffffu, s, o);
        float mean = s * (1.f / DLAT);
        float d0 = v0 - mean, d1 = v1 - mean;
        float d2 = (t + 64 < DLAT) ? (v2 - mean) : 0.f;
        float vs = d0 * d0 + d1 * d1 + d2 * d2;
#pragma unroll
        for (int o = 16; o; o >>= 1) vs += __shfl_xor_sync(0xffffffffu, vs, o);
        float inv = rsqrtf(vs * (1.f / DLAT) + 1e-5f);
        float dot = (d0 * inv * g[t] + be[t]) * Wf[t]
                  + (d1 * inv * g[t + 32] + be[t + 32]) * Wf[t + 32];
        if (t + 64 < DLAT)
            dot += (d2 * inv * g[t + 64] + be[t + 64]) * Wf[t + 64];
#pragma unroll
        for (int o = 16; o; o >>= 1) dot += __shfl_xor_sync(0xffffffffu, dot, o);
        if (t == 0) out[b] = dot + bf[0];
    }
}

// ---------------------------------------------------------------------------
// Launch
// ---------------------------------------------------------------------------
extern "C" void kernel_launch(void* const* d_in, const int* in_sizes, int n_in,
                              void* d_out, int out_size)
{
    const int*   spatial_pos = (const int*)d_in[0];
    const int*   edge_input  = (const int*)d_in[1];
    const int*   x_nodes     = (const int*)d_in[2];
    const int*   indeg       = (const int*)d_in[3];
    const int*   outdeg      = (const int*)d_in[4];
    const float* atom_emb    = (const float*)d_in[5];
    const float* indeg_emb   = (const float*)d_in[6];
    const float* outdeg_emb  = (const float*)d_in[7];
    const float* edge_emb    = (const float*)d_in[8];
    const float* edge_dis_w  = (const float*)d_in[9];
    const float* spatial_emb = (const float*)d_in[10];
    const float* ln1_g = (const float*)d_in[11];
    const float* ln1_b = (const float*)d_in[12];
    const float* Wq    = (const float*)d_in[13];
    const float* Wkv   = (const float*)d_in[14];
    const float* Wo    = (const float*)d_in[15];
    const float* bo    = (const float*)d_in[16];
    const float* ln2_g = (const float*)d_in[17];
    const float* ln2_b = (const float*)d_in[18];
    const float* W1    = (const float*)d_in[19];
    const float* b1    = (const float*)d_in[20];
    const float* W2    = (const float*)d_in[21];
    const float* b2    = (const float*)d_in[22];
    const float* lnf_g = (const float*)d_in[23];
    const float* lnf_b = (const float*)d_in[24];
    const float* Wf    = (const float*)d_in[25];
    const float* bf    = (const float*)d_in[26];
    float* out = (float*)d_out;

    float *gx, *gh, *gqkv, *go, *gf, *gb;
    cudaGetSymbolAddress((void**)&gx,   g_x);
    cudaGetSymbolAddress((void**)&gh,   g_h);
    cudaGetSymbolAddress((void**)&gqkv, g_qkv);
    cudaGetSymbolAddress((void**)&go,   g_o);
    cudaGetSymbolAddress((void**)&gf,   g_f);
    cudaGetSymbolAddress((void**)&gb,   g_bias);

    cudaFuncSetAttribute(attn_kernel,
                         cudaFuncAttributeMaxDynamicSharedMemorySize, ATTN_SMEM);

    bias_kernel<<<BB * NN, 128>>>(spatial_pos, edge_input, edge_emb,
                                  edge_dis_w, spatial_emb, gb);
    embed_kernel<<<ROWS, DLAT>>>(x_nodes, indeg, outdeg,
                                 atom_emb, indeg_emb, outdeg_emb, gx);

    for (int l = 0; l < DEPTH; l++) {
        ln_kernel<<<ROWS / 8, 256>>>(gx, ln1_g + l * DLAT, ln1_b + l * DLAT, gh);
        // Q into cols [0,512), KV into cols [512,1536) of g_qkv (ldc=1536)
        gemm_wide_kernel<<<dim3(INNER / WBN, ROWS / WBM), 256>>>(
            gh, Wq + (long)l * DLAT * INNER, gqkv, ROWS, DLAT, INNER,
            3 * INNER, 0);
        gemm_wide_kernel<<<dim3(2 * INNER / WBN, ROWS / WBM), 256>>>(
            gh, Wkv + (long)l * DLAT * 2 * INNER, gqkv, ROWS, DLAT, 2 * INNER,
            3 * INNER, INNER);
        attn_kernel<<<BB * NH, 256, ATTN_SMEM>>>(gqkv, gb, go);
        gemm_kernel<1><<<dim3(2, ROWS / BM), 256>>>(
            go, Wo + (long)l * INNER * DLAT, bo + l * DLAT, gx,
            gx, ROWS, INNER, DLAT);
        ln_kernel<<<ROWS / 8, 256>>>(gx, ln2_g + l * DLAT, ln2_b + l * DLAT, gh);
        gemm_kernel<2><<<dim3(3, ROWS / BM), 256>>>(
            gh, W1 + (long)l * DLAT * FFD, b1 + l * FFD, nullptr,
            gf, ROWS, DLAT, FFD);
        gemm_kernel<1><<<dim3(2, ROWS / BM), 256>>>(
            gf, W2 + (long)l * FFD * DLAT, b2 + l * DLAT, gx,
            gx, ROWS, FFD, DLAT);
    }

    head_kernel<<<BB, 128>>>(gx, lnf_g, lnf_b, Wf, bf, out);
}

// round 3
// speedup vs baseline: 1.6501x; 1.2786x over previous
#include <cuda_runtime.h>
#include <math.h>

// Problem constants
#define BB 64
#define NN 128
#define DLAT 80
#define NH 8
#define DH 64
#define INNER 512
#define FFD 160
#define MHD 20
#define DEPTH 24
#define ROWS (BB * NN)   // 8192

// ---------------------------------------------------------------------------
// Scratch (device globals; no allocation allowed)
// ---------------------------------------------------------------------------
__device__ float g_x[ROWS * DLAT];          // residual stream
__device__ float g_h[ROWS * DLAT];          // LN output
__device__ float g_qkv[ROWS * 3 * INNER];   // fused Q|K|V (row stride 1536)
__device__ float g_o[ROWS * INNER];         // attention output
__device__ float g_f[ROWS * FFD];           // FF hidden
__device__ float g_bias[BB * NN * NN];      // graph attention bias

// ---------------------------------------------------------------------------
// Graph bias
// ---------------------------------------------------------------------------
__global__ void bias_kernel(const int* __restrict__ spatial_pos,
                            const int* __restrict__ edge_input,
                            const float* __restrict__ edge_emb,
                            const float* __restrict__ edge_dis_w,
                            const float* __restrict__ spatial_emb,
                            float* __restrict__ bias)
{
    __shared__ float s_edge[64];
    __shared__ float s_w[MHD];
    __shared__ float s_sp[40];
    int t = threadIdx.x;               // 128 threads
    if (t < 64) s_edge[t] = edge_emb[t];
    if (t < MHD) s_w[t] = edge_dis_w[t];
    if (t >= 64 && t < 104) s_sp[t - 64] = spatial_emb[t - 64];
    __syncthreads();

    long bi = blockIdx.x;              // b*N + i
    int j = t;
    const int* ei = edge_input + (bi * NN + j) * (MHD * 3);
    float acc = 0.f;
#pragma unroll
    for (int hh = 0; hh < MHD; hh++) {
        float e = (s_edge[ei[hh * 3 + 0]] + s_edge[ei[hh * 3 + 1]] +
                   s_edge[ei[hh * 3 + 2]]) * (1.f / 3.f);
        acc += e * s_w[hh];
    }
    int sp0 = spatial_pos[bi * NN + j];
    int sp = (sp0 == 0) ? 1 : sp0;
    sp = (sp > 1) ? sp - 1 : sp;
    sp = min(sp, MHD);
    bias[bi * NN + j] = acc / (float)sp + s_sp[sp0];
}

// ---------------------------------------------------------------------------
// Node embedding
// ---------------------------------------------------------------------------
__global__ void embed_kernel(const int* __restrict__ x_nodes,
                             const int* __restrict__ indeg,
                             const int* __restrict__ outdeg,
                             const float* __restrict__ atom_emb,
                             const float* __restrict__ indeg_emb,
                             const float* __restrict__ outdeg_emb,
                             float* __restrict__ x)
{
    int r = blockIdx.x;      // 8192 rows
    int d = threadIdx.x;     // 80
    int a = x_nodes[r], i = indeg[r], o = outdeg[r];
    x[(long)r * DLAT + d] = atom_emb[a * DLAT + d] + indeg_emb[i * DLAT + d]
                          + outdeg_emb[o * DLAT + d];
}

// ---------------------------------------------------------------------------
// LayerNorm: one warp per 80-dim row
// ---------------------------------------------------------------------------
__global__ void ln_kernel(const float* __restrict__ x, const float* __restrict__ g,
                          const float* __restrict__ b, float* __restrict__ h)
{
    int w = (blockIdx.x * blockDim.x + threadIdx.x) >> 5;
    int lane = threadIdx.x & 31;
    if (w >= ROWS) return;
    const float* xr = x + (long)w * DLAT;
    float v0 = xr[lane];
    float v1 = xr[lane + 32];
    float v2 = (lane + 64 < DLAT) ? xr[lane + 64] : 0.f;
    float s = v0 + v1 + v2;
#pragma unroll
    for (int o = 16; o; o >>= 1) s += __shfl_xor_sync(0xffffffffu, s, o);
    float mean = s * (1.f / DLAT);
    float d0 = v0 - mean, d1 = v1 - mean;
    float d2 = (lane + 64 < DLAT) ? (v2 - mean) : 0.f;
    float vs = d0 * d0 + d1 * d1 + d2 * d2;
#pragma unroll
    for (int o = 16; o; o >>= 1) vs += __shfl_xor_sync(0xffffffffu, vs, o);
    float inv = rsqrtf(vs * (1.f / DLAT) + 1e-5f);
    float* hr = h + (long)w * DLAT;
    hr[lane]      = d0 * inv * g[lane] + b[lane];
    hr[lane + 32] = d1 * inv * g[lane + 32] + b[lane + 32];
    if (lane + 64 < DLAT)
        hr[lane + 64] = d2 * inv * g[lane + 64] + b[lane + 64];
}

// ---------------------------------------------------------------------------
// tf32 helpers
// ---------------------------------------------------------------------------
__device__ __forceinline__ float to_tf32(float x)
{
    float r;
    asm("cvt.rna.tf32.f32 %0, %1;" : "=f"(r) : "f"(x));
    return r;
}

__device__ __forceinline__ void mma_tf32(float* c, const float* a, const float* b)
{
    asm volatile(
        "mma.sync.aligned.m16n8k8.row.col.f32.tf32.tf32.f32 "
        "{%0,%1,%2,%3}, {%4,%5,%6,%7}, {%8,%9}, {%0,%1,%2,%3};"
        : "+f"(c[0]), "+f"(c[1]), "+f"(c[2]), "+f"(c[3])
        : "r"(__float_as_uint(a[0])), "r"(__float_as_uint(a[1])),
          "r"(__float_as_uint(a[2])), "r"(__float_as_uint(a[3])),
          "r"(__float_as_uint(b[0])), "r"(__float_as_uint(b[1])));
}

// ---------------------------------------------------------------------------
// Wide fp32 GEMM (unchanged): C[m, coff+n] = A[M,K] @ W[K,Nc], row stride ldc.
// ---------------------------------------------------------------------------
#define WBM 128
#define WBN 128
#define WBK 16
#define WAST 132
#define WBST 132

__global__ void __launch_bounds__(256) gemm_wide_kernel(
    const float* __restrict__ A, const float* __restrict__ W,
    float* __restrict__ C, int M, int K, int Nc, int ldc, int coff)
{
    __shared__ float As[WBK * WAST];
    __shared__ float Bs[WBK * WBST];
    int bm = blockIdx.y * WBM;
    int bn = blockIdx.x * WBN;
    int tid = threadIdx.x;
    int tx = tid & 15, ty = tid >> 4;
    float acc[8][8] = {};

    for (int k0 = 0; k0 < K; k0 += WBK) {
        {
            int m = tid >> 1;
            int kq = (tid & 1) * 8;
            const float* ap = A + (long)(bm + m) * K + k0 + kq;
            float4 a0 = *(const float4*)ap;
            float4 a1 = *(const float4*)(ap + 4);
            As[(kq + 0) * WAST + m] = a0.x;
            As[(kq + 1) * WAST + m] = a0.y;
            As[(kq + 2) * WAST + m] = a0.z;
            As[(kq + 3) * WAST + m] = a0.w;
            As[(kq + 4) * WAST + m] = a1.x;
            As[(kq + 5) * WAST + m] = a1.y;
            As[(kq + 6) * WAST + m] = a1.z;
            As[(kq + 7) * WAST + m] = a1.w;
        }
        {
            int k = tid >> 4;
            int nq = (tid & 15) * 8;
            const float* wp = W + (long)(k0 + k) * Nc + bn + nq;
            *(float4*)&Bs[k * WBST + nq]     = *(const float4*)wp;
            *(float4*)&Bs[k * WBST + nq + 4] = *(const float4*)(wp + 4);
        }
        __syncthreads();
#pragma unroll
        for (int kk = 0; kk < WBK; kk++) {
            float a[8], bv[8];
            *(float4*)&a[0]  = *(const float4*)&As[kk * WAST + ty * 8];
            *(float4*)&a[4]  = *(const float4*)&As[kk * WAST + ty * 8 + 4];
            *(float4*)&bv[0] = *(const float4*)&Bs[kk * WBST + tx * 4];
            *(float4*)&bv[4] = *(const float4*)&Bs[kk * WBST + 64 + tx * 4];
#pragma unroll
            for (int i = 0; i < 8; i++)
#pragma unroll
                for (int j = 0; j < 8; j++)
                    acc[i][j] += a[i] * bv[j];
        }
        __syncthreads();
    }
#pragma unroll
    for (int i = 0; i < 8; i++) {
        long m = bm + ty * 8 + i;
#pragma unroll
        for (int jg = 0; jg < 2; jg++) {
            int n = bn + jg * 64 + tx * 4;
            float4 r;
            r.x = acc[i][jg * 4 + 0];
            r.y = acc[i][jg * 4 + 1];
            r.z = acc[i][jg * 4 + 2];
            r.w = acc[i][jg * 4 + 3];
            *(float4*)&C[m * ldc + coff + n] = r;
        }
    }
}

// ---------------------------------------------------------------------------
// Narrow fp32 GEMM (unchanged)
// ---------------------------------------------------------------------------
#define BM 64
#define BN 64
#define BK 16
#define AST (BM + 4)
#define BST (BN + 4)

template <int EPI>
__global__ void __launch_bounds__(256) gemm_kernel(
    const float* __restrict__ A, const float* __restrict__ W,
    const float* __restrict__ bias, const float* __restrict__ res,
    float* __restrict__ C, int M, int K, int Nc)
{
    __shared__ float As[BK * AST];
    __shared__ float Bs[BK * BST];
    int bm = blockIdx.y * BM;
    int bn = blockIdx.x * BN;
    int tid = threadIdx.x;
    int tx = tid & 15, ty = tid >> 4;
    float acc[4][4] = {};

    for (int k0 = 0; k0 < K; k0 += BK) {
        {
            int m = tid >> 2;
            int kq = (tid & 3) * 4;
            float4 a4 = *(const float4*)(A + (long)(bm + m) * K + k0 + kq);
            As[(kq + 0) * AST + m] = a4.x;
            As[(kq + 1) * AST + m] = a4.y;
            As[(kq + 2) * AST + m] = a4.z;
            As[(kq + 3) * AST + m] = a4.w;
        }
        {
            int k = tid >> 4;
            int nq = (tid & 15) * 4;
            int n = bn + nq;
            float4 b4 = make_float4(0.f, 0.f, 0.f, 0.f);
            const float* wp = W + (long)(k0 + k) * Nc;
            if (n + 3 < Nc) {
                b4 = *(const float4*)(wp + n);
            } else if (n < Nc) {
                b4.x = wp[n];
                if (n + 1 < Nc) b4.y = wp[n + 1];
                if (n + 2 < Nc) b4.z = wp[n + 2];
            }
            *(float4*)&Bs[k * BST + nq] = b4;
        }
        __syncthreads();
#pragma unroll
        for (int kk = 0; kk < BK; kk++) {
            float4 a4 = *(const float4*)&As[kk * AST + ty * 4];
            float4 b4 = *(const float4*)&Bs[kk * BST + tx * 4];
            float a[4] = {a4.x, a4.y, a4.z, a4.w};
            float bb[4] = {b4.x, b4.y, b4.z, b4.w};
#pragma unroll
            for (int i = 0; i < 4; i++)
#pragma unroll
                for (int j = 0; j < 4; j++)
                    acc[i][j] += a[i] * bb[j];
        }
        __syncthreads();
    }

#pragma unroll
    for (int i = 0; i < 4; i++) {
        int m = bm + ty * 4 + i;
#pragma unroll
        for (int j = 0; j < 4; j++) {
            int n = bn + tx * 4 + j;
            if (n >= Nc) continue;
            float v = acc[i][j];
            if (EPI == 1) v += bias[n] + res[(long)m * Nc + n];
            if (EPI == 2) {
                v += bias[n];
                v = 0.5f * v * (1.f + erff(v * 0.70710678118654752f));
            }
            C[(long)m * Nc + n] = v;
        }
    }
}

// ---------------------------------------------------------------------------
// Tensor-core attention (tf32 mma.sync), one block per (b,h), 8 warps.
// Warp w owns query rows [16w, 16w+16). Full S row in fragments -> softmax in
// fragment layout -> P via per-warp smem strip -> O = P@V.
// Smem: Q|K|V [128][68] tf32, P [128][132] tf32.  Total 172032 B.
// ---------------------------------------------------------------------------
#define AQS 68
#define APS 132
#define ATTN_SMEM ((3 * NN * AQS + NN * APS) * 4)

__global__ void __launch_bounds__(256, 1) attn_kernel(
    const float* __restrict__ qkv, const float* __restrict__ bias,
    float* __restrict__ o)
{
    extern __shared__ float sm[];
    float* Qs = sm;
    float* Ks = sm + NN * AQS;
    float* Vs = sm + 2 * NN * AQS;
    float* Ps = sm + 3 * NN * AQS;

    int bh = blockIdx.x;
    int b = bh >> 3, h = bh & 7;
    int t = threadIdx.x;

    // Stage Q,K,V rows into smem (tf32-rounded). Thread covers half a row.
    {
        int r = t >> 1;
        int d0 = (t & 1) * 32;
        const float* base = qkv + ((long)(b * NN + r)) * 1536 + h * DH + d0;
        float* qd = Qs + r * AQS + d0;
        float* kd = Ks + r * AQS + d0;
        float* vd = Vs + r * AQS + d0;
#pragma unroll
        for (int i = 0; i < 32; i += 4) {
            float4 q4 = *(const float4*)(base + i);
            float4 k4 = *(const float4*)(base + 512 + i);
            float4 v4 = *(const float4*)(base + 1024 + i);
            qd[i]     = to_tf32(q4.x); qd[i + 1] = to_tf32(q4.y);
            qd[i + 2] = to_tf32(q4.z); qd[i + 3] = to_tf32(q4.w);
            kd[i]     = to_tf32(k4.x); kd[i + 1] = to_tf32(k4.y);
            kd[i + 2] = to_tf32(k4.z); kd[i + 3] = to_tf32(k4.w);
            vd[i]     = to_tf32(v4.x); vd[i + 1] = to_tf32(v4.y);
            vd[i + 2] = to_tf32(v4.z); vd[i + 3] = to_tf32(v4.w);
        }
    }
    __syncthreads();

    int warp = t >> 5, lane = t & 31;
    int g = lane >> 2, tig = lane & 3;
    int m0 = warp * 16;
    int rowL = m0 + g, rowH = m0 + g + 8;

    // Q fragments for all 8 k-tiles (k = d, 64)
    float qa[8][4];
#pragma unroll
    for (int kt = 0; kt < 8; kt++) {
        int k = kt * 8 + tig;
        qa[kt][0] = Qs[rowL * AQS + k];
        qa[kt][1] = Qs[rowH * AQS + k];
        qa[kt][2] = Qs[rowL * AQS + k + 4];
        qa[kt][3] = Qs[rowH * AQS + k + 4];
    }

    // S = Q @ K^T : 16 n-tiles (j), 8 k-tiles (d)
    float sacc[16][4];
#pragma unroll
    for (int nt = 0; nt < 16; nt++) {
        sacc[nt][0] = 0.f; sacc[nt][1] = 0.f;
        sacc[nt][2] = 0.f; sacc[nt][3] = 0.f;
    }
#pragma unroll
    for (int kt = 0; kt < 8; kt++) {
#pragma unroll
        for (int nt = 0; nt < 16; nt++) {
            float bf[2];
            const float* kp = Ks + (nt * 8 + g) * AQS + kt * 8 + tig;
            bf[0] = kp[0];
            bf[1] = kp[4];
            mma_tf32(sacc[nt], qa[kt], bf);
        }
    }

    // scale + bias + row max (rows rowL, rowH; 4 lanes per row)
    const float* bL = bias + ((long)b * NN + rowL) * NN + 2 * tig;
    const float* bH = bias + ((long)b * NN + rowH) * NN + 2 * tig;
    float mx0 = -1e30f, mx1 = -1e30f;
#pragma unroll
    for (int nt = 0; nt < 16; nt++) {
        float2 b0 = *(const float2*)(bL + nt * 8);
        float2 b1 = *(const float2*)(bH + nt * 8);
        sacc[nt][0] = sacc[nt][0] * 0.125f + b0.x;
        sacc[nt][1] = sacc[nt][1] * 0.125f + b0.y;
        sacc[nt][2] = sacc[nt][2] * 0.125f + b1.x;
        sacc[nt][3] = sacc[nt][3] * 0.125f + b1.y;
        mx0 = fmaxf(mx0, fmaxf(sacc[nt][0], sacc[nt][1]));
        mx1 = fmaxf(mx1, fmaxf(sacc[nt][2], sacc[nt][3]));
    }
    mx0 = fmaxf(mx0, __shfl_xor_sync(0xffffffffu, mx0, 1));
    mx0 = fmaxf(mx0, __shfl_xor_sync(0xffffffffu, mx0, 2));
    mx1 = fmaxf(mx1, __shfl_xor_sync(0xffffffffu, mx1, 1));
    mx1 = fmaxf(mx1, __shfl_xor_sync(0xffffffffu, mx1, 2));

    // exp, row sums, store P (tf32) into per-warp smem strip
    float sum0 = 0.f, sum1 = 0.f;
#pragma unroll
    for (int nt = 0; nt < 16; nt++) {
        float p0 = __expf(sacc[nt][0] - mx0);
        float p1 = __expf(sacc[nt][1] - mx0);
        float p2 = __expf(sacc[nt][2] - mx1);
        float p3 = __expf(sacc[nt][3] - mx1);
        sum0 += p0 + p1;
        sum1 += p2 + p3;
        int c = nt * 8 + 2 * tig;
        Ps[rowL * APS + c]     = to_tf32(p0);
        Ps[rowL * APS + c + 1] = to_tf32(p1);
        Ps[rowH * APS + c]     = to_tf32(p2);
        Ps[rowH * APS + c + 1] = to_tf32(p3);
    }
    sum0 += __shfl_xor_sync(0xffffffffu, sum0, 1);
    sum0 += __shfl_xor_sync(0xffffffffu, sum0, 2);
    sum1 += __shfl_xor_sync(0xffffffffu, sum1, 1);
    sum1 += __shfl_xor_sync(0xffffffffu, sum1, 2);
    float inv0 = 1.f / sum0, inv1 = 1.f / sum1;
    __syncwarp();

    // O = P @ V : 16 k-tiles (j), 8 n-tiles (d)
    float oacc[8][4];
#pragma unroll
    for (int nt = 0; nt < 8; nt++) {
        oacc[nt][0] = 0.f; oacc[nt][1] = 0.f;
        oacc[nt][2] = 0.f; oacc[nt][3] = 0.f;
    }
#pragma unroll
    for (int kt = 0; kt < 16; kt++) {
        float pa[4];
        int k = kt * 8 + tig;
        pa[0] = Ps[rowL * APS + k];
        pa[1] = Ps[rowH * APS + k];
        pa[2] = Ps[rowL * APS + k + 4];
        pa[3] = Ps[rowH * APS + k + 4];
#pragma unroll
        for (int nt = 0; nt < 8; nt++) {
            float bf[2];
            bf[0] = Vs[(kt * 8 + tig) * AQS + nt * 8 + g];
            bf[1] = Vs[(kt * 8 + tig + 4) * AQS + nt * 8 + g];
            mma_tf32(oacc[nt], pa, bf);
        }
    }

    // write O (normalize by row sums)
    float* oL = o + ((long)(b * NN + rowL)) * INNER + h * DH;
    float* oH = o + ((long)(b * NN + rowH)) * INNER + h * DH;
#pragma unroll
    for (int nt = 0; nt < 8; nt++) {
        int c = nt * 8 + 2 * tig;
        float2 w0, w1;
        w0.x = oacc[nt][0] * inv0; w0.y = oacc[nt][1] * inv0;
        w1.x = oacc[nt][2] * inv1; w1.y = oacc[nt][3] * inv1;
        *(float2*)&oL[c] = w0;
        *(float2*)&oH[c] = w1;
    }
}

// ---------------------------------------------------------------------------
// Head: mean-pool over N, LayerNorm, dot with Wf
// ---------------------------------------------------------------------------
__global__ void head_kernel(const float* __restrict__ x, const float* __restrict__ g,
                            const float* __restrict__ be, const float* __restrict__ Wf,
                            const float* __restrict__ bf, float* __restrict__ out)
{
    __shared__ float pool[DLAT];
    int b = blockIdx.x;
    int t = threadIdx.x;     // 128 threads
    if (t < DLAT) {
        float s = 0.f;
        const float* xb = x + (long)b * NN * DLAT + t;
        for (int n = 0; n < NN; n++) s += xb[n * DLAT];
        pool[t] = s * (1.f / NN);
    }
    __syncthreads();
    if (t < 32) {
        float v0 = pool[t], v1 = pool[t + 32];
        float v2 = (t + 64 < DLAT) ? pool[t + 64] : 0.f;
        float s = v0 + v1 + v2;
#pragma unroll
        for (int o = 16; o; o >>= 1) s += __shfl_xor_sync(0xffffffffu, s, o);
        float mean = s * (1.f / DLAT);
        float d0 = v0 - mean, d1 = v1 - mean;
        float d2 = (t + 64 < DLAT) ? (v2 - mean) : 0.f;
        float vs = d0 * d0 + d1 * d1 + d2 * d2;
#pragma unroll
        for (int o = 16; o; o >>= 1) vs += __shfl_xor_sync(0xffffffffu, vs, o);
        float inv = rsqrtf(vs * (1.f / DLAT) + 1e-5f);
        float dot = (d0 * inv * g[t] + be[t]) * Wf[t]
                  + (d1 * inv * g[t + 32] + be[t + 32]) * Wf[t + 32];
        if (t + 64 < DLAT)
            dot += (d2 * inv * g[t + 64] + be[t + 64]) * Wf[t + 64];
#pragma unroll
        for (int o = 16; o; o >>= 1) dot += __shfl_xor_sync(0xffffffffu, dot, o);
        if (t == 0) out[b] = dot + bf[0];
    }
}

// ---------------------------------------------------------------------------
// Launch
// ---------------------------------------------------------------------------
extern "C" void kernel_launch(void* const* d_in, const int* in_sizes, int n_in,
                              void* d_out, int out_size)
{
    const int*   spatial_pos = (const int*)d_in[0];
    const int*   edge_input  = (const int*)d_in[1];
    const int*   x_nodes     = (const int*)d_in[2];
    const int*   indeg       = (const int*)d_in[3];
    const int*   outdeg      = (const int*)d_in[4];
    const float* atom_emb    = (const float*)d_in[5];
    const float* indeg_emb   = (const float*)d_in[6];
    const float* outdeg_emb  = (const float*)d_in[7];
    const float* edge_emb    = (const float*)d_in[8];
    const float* edge_dis_w  = (const float*)d_in[9];
    const float* spatial_emb = (const float*)d_in[10];
    const float* ln1_g = (const float*)d_in[11];
    const float* ln1_b = (const float*)d_in[12];
    const float* Wq    = (const float*)d_in[13];
    const float* Wkv   = (const float*)d_in[14];
    const float* Wo    = (const float*)d_in[15];
    const float* bo    = (const float*)d_in[16];
    const float* ln2_g = (const float*)d_in[17];
    const float* ln2_b = (const float*)d_in[18];
    const float* W1    = (const float*)d_in[19];
    const float* b1    = (const float*)d_in[20];
    const float* W2    = (const float*)d_in[21];
    const float* b2    = (const float*)d_in[22];
    const float* lnf_g = (const float*)d_in[23];
    const float* lnf_b = (const float*)d_in[24];
    const float* Wf    = (const float*)d_in[25];
    const float* bf    = (const float*)d_in[26];
    float* out = (float*)d_out;

    float *gx, *gh, *gqkv, *go, *gf, *gb;
    cudaGetSymbolAddress((void**)&gx,   g_x);
    cudaGetSymbolAddress((void**)&gh,   g_h);
    cudaGetSymbolAddress((void**)&gqkv, g_qkv);
    cudaGetSymbolAddress((void**)&go,   g_o);
    cudaGetSymbolAddress((void**)&gf,   g_f);
    cudaGetSymbolAddress((void**)&gb,   g_bias);

    cudaFuncSetAttribute(attn_kernel,
                         cudaFuncAttributeMaxDynamicSharedMemorySize, ATTN_SMEM);

    bias_kernel<<<BB * NN, 128>>>(spatial_pos, edge_input, edge_emb,
                                  edge_dis_w, spatial_emb, gb);
    embed_kernel<<<ROWS, DLAT>>>(x_nodes, indeg, outdeg,
                                 atom_emb, indeg_emb, outdeg_emb, gx);

    for (int l = 0; l < DEPTH; l++) {
        ln_kernel<<<ROWS / 8, 256>>>(gx, ln1_g + l * DLAT, ln1_b + l * DLAT, gh);
        gemm_wide_kernel<<<dim3(INNER / WBN, ROWS / WBM), 256>>>(
            gh, Wq + (long)l * DLAT * INNER, gqkv, ROWS, DLAT, INNER,
            3 * INNER, 0);
        gemm_wide_kernel<<<dim3(2 * INNER / WBN, ROWS / WBM), 256>>>(
            gh, Wkv + (long)l * DLAT * 2 * INNER, gqkv, ROWS, DLAT, 2 * INNER,
            3 * INNER, INNER);
        attn_kernel<<<BB * NH, 256, ATTN_SMEM>>>(gqkv, gb, go);
        gemm_kernel<1><<<dim3(2, ROWS / BM), 256>>>(
            go, Wo + (long)l * INNER * DLAT, bo + l * DLAT, gx,
            gx, ROWS, INNER, DLAT);
        ln_kernel<<<ROWS / 8, 256>>>(gx, ln2_g + l * DLAT, ln2_b + l * DLAT, gh);
        gemm_kernel<2><<<dim3(3, ROWS / BM), 256>>>(
            gh, W1 + (long)l * DLAT * FFD, b1 + l * FFD, nullptr,
            gf, ROWS, DLAT, FFD);
        gemm_kernel<1><<<dim3(2, ROWS / BM), 256>>>(
            gf, W2 + (long)l * FFD * DLAT, b2 + l * DLAT, gx,
            gx, ROWS, FFD, DLAT);
    }

    head_kernel<<<BB, 128>>>(gx, lnf_g, lnf_b, Wf, bf, out);
}

// round 4
// speedup vs baseline: 1.9259x; 1.1671x over previous
#include <cuda_runtime.h>
#include <math.h>

// Problem constants
#define BB 64
#define NN 128
#define DLAT 80
#define NH 8
#define DH 64
#define INNER 512
#define FFD 160
#define MHD 20
#define DEPTH 24
#define ROWS (BB * NN)   // 8192

// ---------------------------------------------------------------------------
// Scratch (device globals; no allocation allowed)
// ---------------------------------------------------------------------------
__device__ float g_x[ROWS * DLAT];          // residual stream
__device__ float g_h[ROWS * DLAT];          // LN output
__device__ float g_qkv[ROWS * 3 * INNER];   // fused Q|K|V (row stride 1536)
__device__ float g_o[ROWS * INNER];         // attention output
__device__ float g_f[ROWS * FFD];           // FF hidden
__device__ float g_bias[BB * NN * NN];      // graph attention bias

// ---------------------------------------------------------------------------
// tf32 helpers
// ---------------------------------------------------------------------------
__device__ __forceinline__ float to_tf32(float x)
{
    float r;
    asm("cvt.rna.tf32.f32 %0, %1;" : "=f"(r) : "f"(x));
    return r;
}

__device__ __forceinline__ void mma_tf32(float* c, const float* a, const float* b)
{
    asm volatile(
        "mma.sync.aligned.m16n8k8.row.col.f32.tf32.tf32.f32 "
        "{%0,%1,%2,%3}, {%4,%5,%6,%7}, {%8,%9}, {%0,%1,%2,%3};"
        : "+f"(c[0]), "+f"(c[1]), "+f"(c[2]), "+f"(c[3])
        : "r"(__float_as_uint(a[0])), "r"(__float_as_uint(a[1])),
          "r"(__float_as_uint(a[2])), "r"(__float_as_uint(a[3])),
          "r"(__float_as_uint(b[0])), "r"(__float_as_uint(b[1])));
}

// ---------------------------------------------------------------------------
// Graph bias
// ---------------------------------------------------------------------------
__global__ void bias_kernel(const int* __restrict__ spatial_pos,
                            const int* __restrict__ edge_input,
                            const float* __restrict__ edge_emb,
                            const float* __restrict__ edge_dis_w,
                            const float* __restrict__ spatial_emb,
                            float* __restrict__ bias)
{
    __shared__ float s_edge[64];
    __shared__ float s_w[MHD];
    __shared__ float s_sp[40];
    int t = threadIdx.x;               // 128 threads
    if (t < 64) s_edge[t] = edge_emb[t];
    if (t < MHD) s_w[t] = edge_dis_w[t];
    if (t >= 64 && t < 104) s_sp[t - 64] = spatial_emb[t - 64];
    __syncthreads();

    long bi = blockIdx.x;              // b*N + i
    int j = t;
    const int* ei = edge_input + (bi * NN + j) * (MHD * 3);
    float acc = 0.f;
#pragma unroll
    for (int hh = 0; hh < MHD; hh++) {
        float e = (s_edge[ei[hh * 3 + 0]] + s_edge[ei[hh * 3 + 1]] +
                   s_edge[ei[hh * 3 + 2]]) * (1.f / 3.f);
        acc += e * s_w[hh];
    }
    int sp0 = spatial_pos[bi * NN + j];
    int sp = (sp0 == 0) ? 1 : sp0;
    sp = (sp > 1) ? sp - 1 : sp;
    sp = min(sp, MHD);
    bias[bi * NN + j] = acc / (float)sp + s_sp[sp0];
}

// ---------------------------------------------------------------------------
// Node embedding
// ---------------------------------------------------------------------------
__global__ void embed_kernel(const int* __restrict__ x_nodes,
                             const int* __restrict__ indeg,
                             const int* __restrict__ outdeg,
                             const float* __restrict__ atom_emb,
                             const float* __restrict__ indeg_emb,
                             const float* __restrict__ outdeg_emb,
                             float* __restrict__ x)
{
    int r = blockIdx.x;      // 8192 rows
    int d = threadIdx.x;     // 80
    int a = x_nodes[r], i = indeg[r], o = outdeg[r];
    x[(long)r * DLAT + d] = atom_emb[a * DLAT + d] + indeg_emb[i * DLAT + d]
                          + outdeg_emb[o * DLAT + d];
}

// ---------------------------------------------------------------------------
// LayerNorm: one warp per 80-dim row
// ---------------------------------------------------------------------------
__global__ void ln_kernel(const float* __restrict__ x, const float* __restrict__ g,
                          const float* __restrict__ b, float* __restrict__ h)
{
    int w = (blockIdx.x * blockDim.x + threadIdx.x) >> 5;
    int lane = threadIdx.x & 31;
    if (w >= ROWS) return;
    const float* xr = x + (long)w * DLAT;
    float v0 = xr[lane];
    float v1 = xr[lane + 32];
    float v2 = (lane + 64 < DLAT) ? xr[lane + 64] : 0.f;
    float s = v0 + v1 + v2;
#pragma unroll
    for (int o = 16; o; o >>= 1) s += __shfl_xor_sync(0xffffffffu, s, o);
    float mean = s * (1.f / DLAT);
    float d0 = v0 - mean, d1 = v1 - mean;
    float d2 = (lane + 64 < DLAT) ? (v2 - mean) : 0.f;
    float vs = d0 * d0 + d1 * d1 + d2 * d2;
#pragma unroll
    for (int o = 16; o; o >>= 1) vs += __shfl_xor_sync(0xffffffffu, vs, o);
    float inv = rsqrtf(vs * (1.f / DLAT) + 1e-5f);
    float* hr = h + (long)w * DLAT;
    hr[lane]      = d0 * inv * g[lane] + b[lane];
    hr[lane + 32] = d1 * inv * g[lane + 32] + b[lane + 32];
    if (lane + 64 < DLAT)
        hr[lane + 64] = d2 * inv * g[lane + 64] + b[lane + 64];
}

// ---------------------------------------------------------------------------
// tf32 tensor-core GEMM: C[m, coff+n] = A[M,K] @ W[K,Nc]  (+ epilogue)
// BM=128, BN=64, BK=16. 8 warps (4m x 2n), warp tile 32x32.
//   EPI 0: plain store (ldc/coff)   EPI 1: +bias[n]+res[m,n]
//   EPI 2: gelu_exact(acc + bias[n])
// Requires M%128==0, K%16==0; Nc arbitrary (guarded).
// Smem row stride 20 -> conflict-free fragment LDS.
// ---------------------------------------------------------------------------
#define GBM 128
#define GBN 64
#define GBK 16
#define GAS 20
#define GBS 20

template <int EPI>
__global__ void __launch_bounds__(256) mma_gemm(
    const float* __restrict__ A, const float* __restrict__ W,
    const float* __restrict__ bias, const float* __restrict__ res,
    float* __restrict__ C, int M, int K, int Nc, int ldc, int coff)
{
    __shared__ float As[GBM * GAS];
    __shared__ float Bs[GBN * GBS];
    int bm = blockIdx.y * GBM;
    int bn = blockIdx.x * GBN;
    int tid = threadIdx.x;
    int warp = tid >> 5, lane = tid & 31;
    int g = lane >> 2, tig = lane & 3;
    int warpM = warp >> 1, warpN = warp & 1;

    float acc[2][4][4];
#pragma unroll
    for (int mt = 0; mt < 2; mt++)
#pragma unroll
        for (int nt = 0; nt < 4; nt++)
#pragma unroll
            for (int i = 0; i < 4; i++) acc[mt][nt][i] = 0.f;

    for (int k0 = 0; k0 < K; k0 += GBK) {
        {   // A tile [128][16] row-major (tf32-rounded)
            int m = tid >> 1;
            int kq = (tid & 1) * 8;
            const float* ap = A + (long)(bm + m) * K + k0 + kq;
            float4 a0 = *(const float4*)ap;
            float4 a1 = *(const float4*)(ap + 4);
            float* ad = As + m * GAS + kq;
            ad[0] = to_tf32(a0.x); ad[1] = to_tf32(a0.y);
            ad[2] = to_tf32(a0.z); ad[3] = to_tf32(a0.w);
            ad[4] = to_tf32(a1.x); ad[5] = to_tf32(a1.y);
            ad[6] = to_tf32(a1.z); ad[7] = to_tf32(a1.w);
        }
        {   // B tile transposed -> Bs[n][k] (tf32), zero-pad n >= Nc
            int kr = tid >> 4;
            int n0 = (tid & 15) * 4;
            const float* wp = W + (long)(k0 + kr) * Nc + bn + n0;
            float4 w4 = make_float4(0.f, 0.f, 0.f, 0.f);
            if (bn + n0 + 3 < Nc) {
                w4 = *(const float4*)wp;
            } else if (bn + n0 < Nc) {
                w4.x = wp[0];
                if (bn + n0 + 1 < Nc) w4.y = wp[1];
                if (bn + n0 + 2 < Nc) w4.z = wp[2];
            }
            Bs[(n0 + 0) * GBS + kr] = to_tf32(w4.x);
            Bs[(n0 + 1) * GBS + kr] = to_tf32(w4.y);
            Bs[(n0 + 2) * GBS + kr] = to_tf32(w4.z);
            Bs[(n0 + 3) * GBS + kr] = to_tf32(w4.w);
        }
        __syncthreads();
#pragma unroll
        for (int kt = 0; kt < 2; kt++) {
            int kk = kt * 8;
            float af[2][4];
#pragma unroll
            for (int mt = 0; mt < 2; mt++) {
                int r = warpM * 32 + mt * 16;
                af[mt][0] = As[(r + g) * GAS + kk + tig];
                af[mt][1] = As[(r + g + 8) * GAS + kk + tig];
                af[mt][2] = As[(r + g) * GAS + kk + tig + 4];
                af[mt][3] = As[(r + g + 8) * GAS + kk + tig + 4];
            }
#pragma unroll
            for (int nt = 0; nt < 4; nt++) {
                float bf[2];
                int n = warpN * 32 + nt * 8 + g;
                bf[0] = Bs[n * GBS + kk + tig];
                bf[1] = Bs[n * GBS + kk + tig + 4];
#pragma unroll
                for (int mt = 0; mt < 2; mt++)
                    mma_tf32(acc[mt][nt], af[mt], bf);
            }
        }
        __syncthreads();
    }

    // Epilogue: thread owns rows (rL, rL+8), cols (n, n+1) per n-tile
#pragma unroll
    for (int mt = 0; mt < 2; mt++) {
        long rL = bm + warpM * 32 + mt * 16 + g;
        long rH = rL + 8;
#pragma unroll
        for (int nt = 0; nt < 4; nt++) {
            int n = bn + warpN * 32 + nt * 8 + 2 * tig;
            if (n >= Nc) continue;   // Nc even -> n,n+1 both valid when n<Nc
            float v0 = acc[mt][nt][0], v1 = acc[mt][nt][1];
            float v2 = acc[mt][nt][2], v3 = acc[mt][nt][3];
            if (EPI == 1) {
                float b0 = bias[n], b1 = bias[n + 1];
                const float* rL_p = res + rL * Nc + n;
                const float* rH_p = res + rH * Nc + n;
                v0 += b0 + rL_p[0]; v1 += b1 + rL_p[1];
                v2 += b0 + rH_p[0]; v3 += b1 + rH_p[1];
            }
            if (EPI == 2) {
                float b0 = bias[n], b1 = bias[n + 1];
                v0 += b0; v1 += b1; v2 += b0; v3 += b1;
                v0 = 0.5f * v0 * (1.f + erff(v0 * 0.70710678118654752f));
                v1 = 0.5f * v1 * (1.f + erff(v1 * 0.70710678118654752f));
                v2 = 0.5f * v2 * (1.f + erff(v2 * 0.70710678118654752f));
                v3 = 0.5f * v3 * (1.f + erff(v3 * 0.70710678118654752f));
            }
            float2 w0, w1;
            w0.x = v0; w0.y = v1;
            w1.x = v2; w1.y = v3;
            *(float2*)&C[rL * ldc + coff + n] = w0;
            *(float2*)&C[rH * ldc + coff + n] = w1;
        }
    }
}

// ---------------------------------------------------------------------------
// Tensor-core attention (tf32 mma.sync), one block per (b,h), 8 warps.
// ---------------------------------------------------------------------------
#define AQS 68
#define APS 132
#define ATTN_SMEM ((3 * NN * AQS + NN * APS) * 4)

__global__ void __launch_bounds__(256, 1) attn_kernel(
    const float* __restrict__ qkv, const float* __restrict__ bias,
    float* __restrict__ o)
{
    extern __shared__ float sm[];
    float* Qs = sm;
    float* Ks = sm + NN * AQS;
    float* Vs = sm + 2 * NN * AQS;
    float* Ps = sm + 3 * NN * AQS;

    int bh = blockIdx.x;
    int b = bh >> 3, h = bh & 7;
    int t = threadIdx.x;

    {
        int r = t >> 1;
        int d0 = (t & 1) * 32;
        const float* base = qkv + ((long)(b * NN + r)) * 1536 + h * DH + d0;
        float* qd = Qs + r * AQS + d0;
        float* kd = Ks + r * AQS + d0;
        float* vd = Vs + r * AQS + d0;
#pragma unroll
        for (int i = 0; i < 32; i += 4) {
            float4 q4 = *(const float4*)(base + i);
            float4 k4 = *(const float4*)(base + 512 + i);
            float4 v4 = *(const float4*)(base + 1024 + i);
            qd[i]     = to_tf32(q4.x); qd[i + 1] = to_tf32(q4.y);
            qd[i + 2] = to_tf32(q4.z); qd[i + 3] = to_tf32(q4.w);
            kd[i]     = to_tf32(k4.x); kd[i + 1] = to_tf32(k4.y);
            kd[i + 2] = to_tf32(k4.z); kd[i + 3] = to_tf32(k4.w);
            vd[i]     = to_tf32(v4.x); vd[i + 1] = to_tf32(v4.y);
            vd[i + 2] = to_tf32(v4.z); vd[i + 3] = to_tf32(v4.w);
        }
    }
    __syncthreads();

    int warp = t >> 5, lane = t & 31;
    int g = lane >> 2, tig = lane & 3;
    int m0 = warp * 16;
    int rowL = m0 + g, rowH = m0 + g + 8;

    float qa[8][4];
#pragma unroll
    for (int kt = 0; kt < 8; kt++) {
        int k = kt * 8 + tig;
        qa[kt][0] = Qs[rowL * AQS + k];
        qa[kt][1] = Qs[rowH * AQS + k];
        qa[kt][2] = Qs[rowL * AQS + k + 4];
        qa[kt][3] = Qs[rowH * AQS + k + 4];
    }

    float sacc[16][4];
#pragma unroll
    for (int nt = 0; nt < 16; nt++) {
        sacc[nt][0] = 0.f; sacc[nt][1] = 0.f;
        sacc[nt][2] = 0.f; sacc[nt][3] = 0.f;
    }
#pragma unroll
    for (int kt = 0; kt < 8; kt++) {
#pragma unroll
        for (int nt = 0; nt < 16; nt++) {
            float bf[2];
            const float* kp = Ks + (nt * 8 + g) * AQS + kt * 8 + tig;
            bf[0] = kp[0];
            bf[1] = kp[4];
            mma_tf32(sacc[nt], qa[kt], bf);
        }
    }

    const float* bL = bias + ((long)b * NN + rowL) * NN + 2 * tig;
    const float* bH = bias + ((long)b * NN + rowH) * NN + 2 * tig;
    float mx0 = -1e30f, mx1 = -1e30f;
#pragma unroll
    for (int nt = 0; nt < 16; nt++) {
        float2 b0 = *(const float2*)(bL + nt * 8);
        float2 b1 = *(const float2*)(bH + nt * 8);
        sacc[nt][0] = sacc[nt][0] * 0.125f + b0.x;
        sacc[nt][1] = sacc[nt][1] * 0.125f + b0.y;
        sacc[nt][2] = sacc[nt][2] * 0.125f + b1.x;
        sacc[nt][3] = sacc[nt][3] * 0.125f + b1.y;
        mx0 = fmaxf(mx0, fmaxf(sacc[nt][0], sacc[nt][1]));
        mx1 = fmaxf(mx1, fmaxf(sacc[nt][2], sacc[nt][3]));
    }
    mx0 = fmaxf(mx0, __shfl_xor_sync(0xffffffffu, mx0, 1));
    mx0 = fmaxf(mx0, __shfl_xor_sync(0xffffffffu, mx0, 2));
    mx1 = fmaxf(mx1, __shfl_xor_sync(0xffffffffu, mx1, 1));
    mx1 = fmaxf(mx1, __shfl_xor_sync(0xffffffffu, mx1, 2));

    float sum0 = 0.f, sum1 = 0.f;
#pragma unroll
    for (int nt = 0; nt < 16; nt++) {
        float p0 = __expf(sacc[nt][0] - mx0);
        float p1 = __expf(sacc[nt][1] - mx0);
        float p2 = __expf(sacc[nt][2] - mx1);
        float p3 = __expf(sacc[nt][3] - mx1);
        sum0 += p0 + p1;
        sum1 += p2 + p3;
        int c = nt * 8 + 2 * tig;
        Ps[rowL * APS + c]     = to_tf32(p0);
        Ps[rowL * APS + c + 1] = to_tf32(p1);
        Ps[rowH * APS + c]     = to_tf32(p2);
        Ps[rowH * APS + c + 1] = to_tf32(p3);
    }
    sum0 += __shfl_xor_sync(0xffffffffu, sum0, 1);
    sum0 += __shfl_xor_sync(0xffffffffu, sum0, 2);
    sum1 += __shfl_xor_sync(0xffffffffu, sum1, 1);
    sum1 += __shfl_xor_sync(0xffffffffu, sum1, 2);
    float inv0 = 1.f / sum0, inv1 = 1.f / sum1;
    __syncwarp();

    float oacc[8][4];
#pragma unroll
    for (int nt = 0; nt < 8; nt++) {
        oacc[nt][0] = 0.f; oacc[nt][1] = 0.f;
        oacc[nt][2] = 0.f; oacc[nt][3] = 0.f;
    }
#pragma unroll
    for (int kt = 0; kt < 16; kt++) {
        float pa[4];
        int k = kt * 8 + tig;
        pa[0] = Ps[rowL * APS + k];
        pa[1] = Ps[rowH * APS + k];
        pa[2] = Ps[rowL * APS + k + 4];
        pa[3] = Ps[rowH * APS + k + 4];
#pragma unroll
        for (int nt = 0; nt < 8; nt++) {
            float bf[2];
            bf[0] = Vs[(kt * 8 + tig) * AQS + nt * 8 + g];
            bf[1] = Vs[(kt * 8 + tig + 4) * AQS + nt * 8 + g];
            mma_tf32(oacc[nt], pa, bf);
        }
    }

    float* oL = o + ((long)(b * NN + rowL)) * INNER + h * DH;
    float* oH = o + ((long)(b * NN + rowH)) * INNER + h * DH;
#pragma unroll
    for (int nt = 0; nt < 8; nt++) {
        int c = nt * 8 + 2 * tig;
        float2 w0, w1;
        w0.x = oacc[nt][0] * inv0; w0.y = oacc[nt][1] * inv0;
        w1.x = oacc[nt][2] * inv1; w1.y = oacc[nt][3] * inv1;
        *(float2*)&oL[c] = w0;
        *(float2*)&oH[c] = w1;
    }
}

// ---------------------------------------------------------------------------
// Head: mean-pool over N, LayerNorm, dot with Wf
// ---------------------------------------------------------------------------
__global__ void head_kernel(const float* __restrict__ x, const float* __restrict__ g,
                            const float* __restrict__ be, const float* __restrict__ Wf,
                            const float* __restrict__ bf, float* __restrict__ out)
{
    __shared__ float pool[DLAT];
    int b = blockIdx.x;
    int t = threadIdx.x;     // 128 threads
    if (t < DLAT) {
        float s = 0.f;
        const float* xb = x + (long)b * NN * DLAT + t;
        for (int n = 0; n < NN; n++) s += xb[n * DLAT];
        pool[t] = s * (1.f / NN);
    }
    __syncthreads();
    if (t < 32) {
        float v0 = pool[t], v1 = pool[t + 32];
        float v2 = (t + 64 < DLAT) ? pool[t + 64] : 0.f;
        float s = v0 + v1 + v2;
#pragma unroll
        for (int o = 16; o; o >>= 1) s += __shfl_xor_sync(0xffffffffu, s, o);
        float mean = s * (1.f / DLAT);
        float d0 = v0 - mean, d1 = v1 - mean;
        float d2 = (t + 64 < DLAT) ? (v2 - mean) : 0.f;
        float vs = d0 * d0 + d1 * d1 + d2 * d2;
#pragma unroll
        for (int o = 16; o; o >>= 1) vs += __shfl_xor_sync(0xffffffffu, vs, o);
        float inv = rsqrtf(vs * (1.f / DLAT) + 1e-5f);
        float dot = (d0 * inv * g[t] + be[t]) * Wf[t]
                  + (d1 * inv * g[t + 32] + be[t + 32]) * Wf[t + 32];
        if (t + 64 < DLAT)
            dot += (d2 * inv * g[t + 64] + be[t + 64]) * Wf[t + 64];
#pragma unroll
        for (int o = 16; o; o >>= 1) dot += __shfl_xor_sync(0xffffffffu, dot, o);
        if (t == 0) out[b] = dot + bf[0];
    }
}

// ---------------------------------------------------------------------------
// Launch
// ---------------------------------------------------------------------------
extern "C" void kernel_launch(void* const* d_in, const int* in_sizes, int n_in,
                              void* d_out, int out_size)
{
    const int*   spatial_pos = (const int*)d_in[0];
    const int*   edge_input  = (const int*)d_in[1];
    const int*   x_nodes     = (const int*)d_in[2];
    const int*   indeg       = (const int*)d_in[3];
    const int*   outdeg      = (const int*)d_in[4];
    const float* atom_emb    = (const float*)d_in[5];
    const float* indeg_emb   = (const float*)d_in[6];
    const float* outdeg_emb  = (const float*)d_in[7];
    const float* edge_emb    = (const float*)d_in[8];
    const float* edge_dis_w  = (const float*)d_in[9];
    const float* spatial_emb = (const float*)d_in[10];
    const float* ln1_g = (const float*)d_in[11];
    const float* ln1_b = (const float*)d_in[12];
    const float* Wq    = (const float*)d_in[13];
    const float* Wkv   = (const float*)d_in[14];
    const float* Wo    = (const float*)d_in[15];
    const float* bo    = (const float*)d_in[16];
    const float* ln2_g = (const float*)d_in[17];
    const float* ln2_b = (const float*)d_in[18];
    const float* W1    = (const float*)d_in[19];
    const float* b1    = (const float*)d_in[20];
    const float* W2    = (const float*)d_in[21];
    const float* b2    = (const float*)d_in[22];
    const float* lnf_g = (const float*)d_in[23];
    const float* lnf_b = (const float*)d_in[24];
    const float* Wf    = (const float*)d_in[25];
    const float* bf    = (const float*)d_in[26];
    float* out = (float*)d_out;

    float *gx, *gh, *gqkv, *go, *gf, *gb;
    cudaGetSymbolAddress((void**)&gx,   g_x);
    cudaGetSymbolAddress((void**)&gh,   g_h);
    cudaGetSymbolAddress((void**)&gqkv, g_qkv);
    cudaGetSymbolAddress((void**)&go,   g_o);
    cudaGetSymbolAddress((void**)&gf,   g_f);
    cudaGetSymbolAddress((void**)&gb,   g_bias);

    cudaFuncSetAttribute(attn_kernel,
                         cudaFuncAttributeMaxDynamicSharedMemorySize, ATTN_SMEM);

    bias_kernel<<<BB * NN, 128>>>(spatial_pos, edge_input, edge_emb,
                                  edge_dis_w, spatial_emb, gb);
    embed_kernel<<<ROWS, DLAT>>>(x_nodes, indeg, outdeg,
                                 atom_emb, indeg_emb, outdeg_emb, gx);

    for (int l = 0; l < DEPTH; l++) {
        ln_kernel<<<ROWS / 8, 256>>>(gx, ln1_g + l * DLAT, ln1_b + l * DLAT, gh);
        // QKV (fused buffer, ldc=1536): Q cols [0,512), KV cols [512,1536)
        mma_gemm<0><<<dim3(INNER / GBN, ROWS / GBM), 256>>>(
            gh, Wq + (long)l * DLAT * INNER, nullptr, nullptr,
            gqkv, ROWS, DLAT, INNER, 3 * INNER, 0);
        mma_gemm<0><<<dim3(2 * INNER / GBN, ROWS / GBM), 256>>>(
            gh, Wkv + (long)l * DLAT * 2 * INNER, nullptr, nullptr,
            gqkv, ROWS, DLAT, 2 * INNER, 3 * INNER, INNER);
        attn_kernel<<<BB * NH, 256, ATTN_SMEM>>>(gqkv, gb, go);
        mma_gemm<1><<<dim3(2, ROWS / GBM), 256>>>(
            go, Wo + (long)l * INNER * DLAT, bo + l * DLAT, gx,
            gx, ROWS, INNER, DLAT, DLAT, 0);
        ln_kernel<<<ROWS / 8, 256>>>(gx, ln2_g + l * DLAT, ln2_b + l * DLAT, gh);
        mma_gemm<2><<<dim3(3, ROWS / GBM), 256>>>(
            gh, W1 + (long)l * DLAT * FFD, b1 + l * FFD, nullptr,
            gf, ROWS, DLAT, FFD, FFD, 0);
        mma_gemm<1><<<dim3(2, ROWS / GBM), 256>>>(
            gf, W2 + (long)l * FFD * DLAT, b2 + l * DLAT, gx,
            gx, ROWS, FFD, DLAT, DLAT, 0);
    }

    head_kernel<<<BB, 128>>>(gx, lnf_g, lnf_b, Wf, bf, out);
}

// round 5
// speedup vs baseline: 1.9297x; 1.0020x over previous
#include <cuda_runtime.h>
#include <math.h>

// Problem constants
#define BB 64
#define NN 128
#define DLAT 80
#define NH 8
#define DH 64
#define INNER 512
#define FFD 160
#define MHD 20
#define DEPTH 24
#define ROWS (BB * NN)   // 8192

// ---------------------------------------------------------------------------
// Scratch (device globals; no allocation allowed)
// ---------------------------------------------------------------------------
__device__ float g_x[ROWS * DLAT];          // residual stream
__device__ float g_qkv[ROWS * 3 * INNER];   // fused Q|K|V (row stride 1536)
__device__ float g_o[ROWS * INNER];         // attention output
__device__ float g_f[ROWS * FFD];           // FF hidden
__device__ float g_bias[BB * NN * NN];      // graph attention bias

// ---------------------------------------------------------------------------
// tf32 helpers
// ---------------------------------------------------------------------------
__device__ __forceinline__ float to_tf32(float x)
{
    float r;
    asm("cvt.rna.tf32.f32 %0, %1;" : "=f"(r) : "f"(x));
    return r;
}

__device__ __forceinline__ void mma_tf32(float* c, const float* a, const float* b)
{
    asm volatile(
        "mma.sync.aligned.m16n8k8.row.col.f32.tf32.tf32.f32 "
        "{%0,%1,%2,%3}, {%4,%5,%6,%7}, {%8,%9}, {%0,%1,%2,%3};"
        : "+f"(c[0]), "+f"(c[1]), "+f"(c[2]), "+f"(c[3])
        : "r"(__float_as_uint(a[0])), "r"(__float_as_uint(a[1])),
          "r"(__float_as_uint(a[2])), "r"(__float_as_uint(a[3])),
          "r"(__float_as_uint(b[0])), "r"(__float_as_uint(b[1])));
}

// ---------------------------------------------------------------------------
// Graph bias
// ---------------------------------------------------------------------------
__global__ void bias_kernel(const int* __restrict__ spatial_pos,
                            const int* __restrict__ edge_input,
                            const float* __restrict__ edge_emb,
                            const float* __restrict__ edge_dis_w,
                            const float* __restrict__ spatial_emb,
                            float* __restrict__ bias)
{
    __shared__ float s_edge[64];
    __shared__ float s_w[MHD];
    __shared__ float s_sp[40];
    int t = threadIdx.x;               // 128 threads
    if (t < 64) s_edge[t] = edge_emb[t];
    if (t < MHD) s_w[t] = edge_dis_w[t];
    if (t >= 64 && t < 104) s_sp[t - 64] = spatial_emb[t - 64];
    __syncthreads();

    long bi = blockIdx.x;              // b*N + i
    int j = t;
    const int* ei = edge_input + (bi * NN + j) * (MHD * 3);
    float acc = 0.f;
#pragma unroll
    for (int hh = 0; hh < MHD; hh++) {
        float e = (s_edge[ei[hh * 3 + 0]] + s_edge[ei[hh * 3 + 1]] +
                   s_edge[ei[hh * 3 + 2]]) * (1.f / 3.f);
        acc += e * s_w[hh];
    }
    int sp0 = spatial_pos[bi * NN + j];
    int sp = (sp0 == 0) ? 1 : sp0;
    sp = (sp > 1) ? sp - 1 : sp;
    sp = min(sp, MHD);
    bias[bi * NN + j] = acc / (float)sp + s_sp[sp0];
}

// ---------------------------------------------------------------------------
// Node embedding
// ---------------------------------------------------------------------------
__global__ void embed_kernel(const int* __restrict__ x_nodes,
                             const int* __restrict__ indeg,
                             const int* __restrict__ outdeg,
                             const float* __restrict__ atom_emb,
                             const float* __restrict__ indeg_emb,
                             const float* __restrict__ outdeg_emb,
                             float* __restrict__ x)
{
    int r = blockIdx.x;      // 8192 rows
    int d = threadIdx.x;     // 80
    int a = x_nodes[r], i = indeg[r], o = outdeg[r];
    x[(long)r * DLAT + d] = atom_emb[a * DLAT + d] + indeg_emb[i * DLAT + d]
                          + outdeg_emb[o * DLAT + d];
}

// ---------------------------------------------------------------------------
// Panel GEMM with fused LayerNorm (K = DLAT = 80 only).
// C[m, n] = LN(X)[m,:] @ W[:, n] (+ epilogue), whole panels staged in smem,
// ONE __syncthreads, then 10 k-tiles of mma without further syncs.
// Dual-weight: block cols < NcA read Wa, else Wb (for fused Q|KV).
//   EPI 0: plain store     EPI 2: gelu_exact(acc + bias[n])
// ---------------------------------------------------------------------------
#define PAST 84
#define PANEL_SMEM ((128 + 64) * PAST * 4)   // 64512 bytes

template <int EPI>
__global__ void __launch_bounds__(256) panel_gemm(
    const float* __restrict__ X,
    const float* __restrict__ lng, const float* __restrict__ lnb,
    const float* __restrict__ Wa, const float* __restrict__ Wb,
    int NcA, int NcB,
    const float* __restrict__ bias,
    float* __restrict__ C, int ldc)
{
    extern __shared__ float smp[];
    float* As = smp;                // [128][84]
    float* Bs = smp + 128 * PAST;   // [64][84]

    int bm = blockIdx.y * 128;
    int n_glob = blockIdx.x * 64;
    const float* W; int Wn; int wcol;
    if (n_glob < NcA) { W = Wa; Wn = NcA; wcol = n_glob; }
    else             { W = Wb; Wn = NcB; wcol = n_glob - NcA; }
    int NcTot = NcA + NcB;

    int t = threadIdx.x;

    // --- A panel: load 128x80, fused LayerNorm, tf32 store ---
    {
        int r = t >> 1, half = t & 1;
        const float* ar = X + (long)(bm + r) * DLAT + half * 40;
        float* ad = As + r * PAST + half * 40;
        float s = 0.f;
#pragma unroll
        for (int i = 0; i < 40; i += 4) {
            float4 a4 = *(const float4*)(ar + i);
            *(float4*)(ad + i) = a4;
            s += (a4.x + a4.y) + (a4.z + a4.w);
        }
        s += __shfl_xor_sync(0xffffffffu, s, 1);
        float mean = s * (1.f / DLAT);
        float vs = 0.f;
#pragma unroll
        for (int i = 0; i < 40; i++) { float d = ad[i] - mean; vs += d * d; }
        vs += __shfl_xor_sync(0xffffffffu, vs, 1);
        float inv = rsqrtf(vs * (1.f / DLAT) + 1e-5f);
        const float* gg = lng + half * 40;
        const float* bb = lnb + half * 40;
#pragma unroll
        for (int i = 0; i < 40; i++)
            ad[i] = to_tf32((ad[i] - mean) * inv * gg[i] + bb[i]);
    }

    // --- B panel: transpose-stage W[k][wcol+n] -> Bs[n][k] (tf32) ---
    {
        int kr = t >> 4;          // 0..15
        int n0 = (t & 15) * 4;    // 0..60
#pragma unroll
        for (int kb = 0; kb < DLAT; kb += 16) {
            int k = kb + kr;
            float4 w4 = make_float4(0.f, 0.f, 0.f, 0.f);
            if (wcol + n0 < Wn) {
                const float* wp = W + (long)k * Wn + wcol + n0;
                if (wcol + n0 + 3 < Wn) {
                    w4 = *(const float4*)wp;
                } else {
                    w4.x = wp[0];
                    if (wcol + n0 + 1 < Wn) w4.y = wp[1];
                    if (wcol + n0 + 2 < Wn) w4.z = wp[2];
                }
            }
            Bs[(n0 + 0) * PAST + k] = to_tf32(w4.x);
            Bs[(n0 + 1) * PAST + k] = to_tf32(w4.y);
            Bs[(n0 + 2) * PAST + k] = to_tf32(w4.z);
            Bs[(n0 + 3) * PAST + k] = to_tf32(w4.w);
        }
    }
    __syncthreads();

    int warp = t >> 5, lane = t & 31;
    int g = lane >> 2, tig = lane & 3;
    int warpM = warp >> 1, warpN = warp & 1;

    float acc[2][4][4] = {};

#pragma unroll
    for (int kt = 0; kt < 10; kt++) {
        int kk = kt * 8;
        float af[2][4];
#pragma unroll
        for (int mt = 0; mt < 2; mt++) {
            int r = warpM * 32 + mt * 16;
            af[mt][0] = As[(r + g) * PAST + kk + tig];
            af[mt][1] = As[(r + g + 8) * PAST + kk + tig];
            af[mt][2] = As[(r + g) * PAST + kk + tig + 4];
            af[mt][3] = As[(r + g + 8) * PAST + kk + tig + 4];
        }
#pragma unroll
        for (int nt = 0; nt < 4; nt++) {
            float bf[2];
            int n = warpN * 32 + nt * 8 + g;
            bf[0] = Bs[n * PAST + kk + tig];
            bf[1] = Bs[n * PAST + kk + tig + 4];
#pragma unroll
            for (int mt = 0; mt < 2; mt++)
                mma_tf32(acc[mt][nt], af[mt], bf);
        }
    }

#pragma unroll
    for (int mt = 0; mt < 2; mt++) {
        long rL = bm + warpM * 32 + mt * 16 + g;
        long rH = rL + 8;
#pragma unroll
        for (int nt = 0; nt < 4; nt++) {
            int n = n_glob + warpN * 32 + nt * 8 + 2 * tig;
            if (n >= NcTot) continue;
            float v0 = acc[mt][nt][0], v1 = acc[mt][nt][1];
            float v2 = acc[mt][nt][2], v3 = acc[mt][nt][3];
            if (EPI == 2) {
                float b0 = bias[n], b1 = bias[n + 1];
                v0 += b0; v1 += b1; v2 += b0; v3 += b1;
                v0 = 0.5f * v0 * (1.f + erff(v0 * 0.70710678118654752f));
                v1 = 0.5f * v1 * (1.f + erff(v1 * 0.70710678118654752f));
                v2 = 0.5f * v2 * (1.f + erff(v2 * 0.70710678118654752f));
                v3 = 0.5f * v3 * (1.f + erff(v3 * 0.70710678118654752f));
            }
            float2 w0, w1;
            w0.x = v0; w0.y = v1;
            w1.x = v2; w1.y = v3;
            *(float2*)&C[rL * ldc + n] = w0;
            *(float2*)&C[rH * ldc + n] = w1;
        }
    }
}

// ---------------------------------------------------------------------------
// Chunked tf32 GEMM (K-loop) for Wo (K=512) and FF2 (K=160).
//   EPI 1: +bias[n]+res[m,n]
// ---------------------------------------------------------------------------
#define GBM 128
#define GBN 64
#define GBK 16
#define GAS 20
#define GBS 20

template <int EPI>
__global__ void __launch_bounds__(256) mma_gemm(
    const float* __restrict__ A, const float* __restrict__ W,
    const float* __restrict__ bias, const float* __restrict__ res,
    float* __restrict__ C, int M, int K, int Nc, int ldc, int coff)
{
    __shared__ float As[GBM * GAS];
    __shared__ float Bs[GBN * GBS];
    int bm = blockIdx.y * GBM;
    int bn = blockIdx.x * GBN;
    int tid = threadIdx.x;
    int warp = tid >> 5, lane = tid & 31;
    int g = lane >> 2, tig = lane & 3;
    int warpM = warp >> 1, warpN = warp & 1;

    float acc[2][4][4] = {};

    for (int k0 = 0; k0 < K; k0 += GBK) {
        {
            int m = tid >> 1;
            int kq = (tid & 1) * 8;
            const float* ap = A + (long)(bm + m) * K + k0 + kq;
            float4 a0 = *(const float4*)ap;
            float4 a1 = *(const float4*)(ap + 4);
            float* ad = As + m * GAS + kq;
            ad[0] = to_tf32(a0.x); ad[1] = to_tf32(a0.y);
            ad[2] = to_tf32(a0.z); ad[3] = to_tf32(a0.w);
            ad[4] = to_tf32(a1.x); ad[5] = to_tf32(a1.y);
            ad[6] = to_tf32(a1.z); ad[7] = to_tf32(a1.w);
        }
        {
            int kr = tid >> 4;
            int n0 = (tid & 15) * 4;
            const float* wp = W + (long)(k0 + kr) * Nc + bn + n0;
            float4 w4 = make_float4(0.f, 0.f, 0.f, 0.f);
            if (bn + n0 + 3 < Nc) {
                w4 = *(const float4*)wp;
            } else if (bn + n0 < Nc) {
                w4.x = wp[0];
                if (bn + n0 + 1 < Nc) w4.y = wp[1];
                if (bn + n0 + 2 < Nc) w4.z = wp[2];
            }
            Bs[(n0 + 0) * GBS + kr] = to_tf32(w4.x);
            Bs[(n0 + 1) * GBS + kr] = to_tf32(w4.y);
            Bs[(n0 + 2) * GBS + kr] = to_tf32(w4.z);
            Bs[(n0 + 3) * GBS + kr] = to_tf32(w4.w);
        }
        __syncthreads();
#pragma unroll
        for (int kt = 0; kt < 2; kt++) {
            int kk = kt * 8;
            float af[2][4];
#pragma unroll
            for (int mt = 0; mt < 2; mt++) {
                int r = warpM * 32 + mt * 16;
                af[mt][0] = As[(r + g) * GAS + kk + tig];
                af[mt][1] = As[(r + g + 8) * GAS + kk + tig];
                af[mt][2] = As[(r + g) * GAS + kk + tig + 4];
                af[mt][3] = As[(r + g + 8) * GAS + kk + tig + 4];
            }
#pragma unroll
            for (int nt = 0; nt < 4; nt++) {
                float bf[2];
                int n = warpN * 32 + nt * 8 + g;
                bf[0] = Bs[n * GBS + kk + tig];
                bf[1] = Bs[n * GBS + kk + tig + 4];
#pragma unroll
                for (int mt = 0; mt < 2; mt++)
                    mma_tf32(acc[mt][nt], af[mt], bf);
            }
        }
        __syncthreads();
    }

#pragma unroll
    for (int mt = 0; mt < 2; mt++) {
        long rL = bm + warpM * 32 + mt * 16 + g;
        long rH = rL + 8;
#pragma unroll
        for (int nt = 0; nt < 4; nt++) {
            int n = bn + warpN * 32 + nt * 8 + 2 * tig;
            if (n >= Nc) continue;
            float v0 = acc[mt][nt][0], v1 = acc[mt][nt][1];
            float v2 = acc[mt][nt][2], v3 = acc[mt][nt][3];
            if (EPI == 1) {
                float b0 = bias[n], b1 = bias[n + 1];
                const float* rL_p = res + rL * Nc + n;
                const float* rH_p = res + rH * Nc + n;
                v0 += b0 + rL_p[0]; v1 += b1 + rL_p[1];
                v2 += b0 + rH_p[0]; v3 += b1 + rH_p[1];
            }
            float2 w0, w1;
            w0.x = v0; w0.y = v1;
            w1.x = v2; w1.y = v3;
            *(float2*)&C[rL * ldc + coff + n] = w0;
            *(float2*)&C[rH * ldc + coff + n] = w1;
        }
    }
}

// ---------------------------------------------------------------------------
// Tensor-core attention (tf32 mma.sync), one block per (b,h), 8 warps.
// ---------------------------------------------------------------------------
#define AQS 68
#define APS 132
#define ATTN_SMEM ((3 * NN * AQS + NN * APS) * 4)

__global__ void __launch_bounds__(256, 1) attn_kernel(
    const float* __restrict__ qkv, const float* __restrict__ bias,
    float* __restrict__ o)
{
    extern __shared__ float sm[];
    float* Qs = sm;
    float* Ks = sm + NN * AQS;
    float* Vs = sm + 2 * NN * AQS;
    float* Ps = sm + 3 * NN * AQS;

    int bh = blockIdx.x;
    int b = bh >> 3, h = bh & 7;
    int t = threadIdx.x;

    {
        int r = t >> 1;
        int d0 = (t & 1) * 32;
        const float* base = qkv + ((long)(b * NN + r)) * 1536 + h * DH + d0;
        float* qd = Qs + r * AQS + d0;
        float* kd = Ks + r * AQS + d0;
        float* vd = Vs + r * AQS + d0;
#pragma unroll
        for (int i = 0; i < 32; i += 4) {
            float4 q4 = *(const float4*)(base + i);
            float4 k4 = *(const float4*)(base + 512 + i);
            float4 v4 = *(const float4*)(base + 1024 + i);
            qd[i]     = to_tf32(q4.x); qd[i + 1] = to_tf32(q4.y);
            qd[i + 2] = to_tf32(q4.z); qd[i + 3] = to_tf32(q4.w);
            kd[i]     = to_tf32(k4.x); kd[i + 1] = to_tf32(k4.y);
            kd[i + 2] = to_tf32(k4.z); kd[i + 3] = to_tf32(k4.w);
            vd[i]     = to_tf32(v4.x); vd[i + 1] = to_tf32(v4.y);
            vd[i + 2] = to_tf32(v4.z); vd[i + 3] = to_tf32(v4.w);
        }
    }
    __syncthreads();

    int warp = t >> 5, lane = t & 31;
    int g = lane >> 2, tig = lane & 3;
    int m0 = warp * 16;
    int rowL = m0 + g, rowH = m0 + g + 8;

    float qa[8][4];
#pragma unroll
    for (int kt = 0; kt < 8; kt++) {
        int k = kt * 8 + tig;
        qa[kt][0] = Qs[rowL * AQS + k];
        qa[kt][1] = Qs[rowH * AQS + k];
        qa[kt][2] = Qs[rowL * AQS + k + 4];
        qa[kt][3] = Qs[rowH * AQS + k + 4];
    }

    float sacc[16][4];
#pragma unroll
    for (int nt = 0; nt < 16; nt++) {
        sacc[nt][0] = 0.f; sacc[nt][1] = 0.f;
        sacc[nt][2] = 0.f; sacc[nt][3] = 0.f;
    }
#pragma unroll
    for (int kt = 0; kt < 8; kt++) {
#pragma unroll
        for (int nt = 0; nt < 16; nt++) {
            float bf[2];
            const float* kp = Ks + (nt * 8 + g) * AQS + kt * 8 + tig;
            bf[0] = kp[0];
            bf[1] = kp[4];
            mma_tf32(sacc[nt], qa[kt], bf);
        }
    }

    const float* bL = bias + ((long)b * NN + rowL) * NN + 2 * tig;
    const float* bH = bias + ((long)b * NN + rowH) * NN + 2 * tig;
    float mx0 = -1e30f, mx1 = -1e30f;
#pragma unroll
    for (int nt = 0; nt < 16; nt++) {
        float2 b0 = *(const float2*)(bL + nt * 8);
        float2 b1 = *(const float2*)(bH + nt * 8);
        sacc[nt][0] = sacc[nt][0] * 0.125f + b0.x;
        sacc[nt][1] = sacc[nt][1] * 0.125f + b0.y;
        sacc[nt][2] = sacc[nt][2] * 0.125f + b1.x;
        sacc[nt][3] = sacc[nt][3] * 0.125f + b1.y;
        mx0 = fmaxf(mx0, fmaxf(sacc[nt][0], sacc[nt][1]));
        mx1 = fmaxf(mx1, fmaxf(sacc[nt][2], sacc[nt][3]));
    }
    mx0 = fmaxf(mx0, __shfl_xor_sync(0xffffffffu, mx0, 1));
    mx0 = fmaxf(mx0, __shfl_xor_sync(0xffffffffu, mx0, 2));
    mx1 = fmaxf(mx1, __shfl_xor_sync(0xffffffffu, mx1, 1));
    mx1 = fmaxf(mx1, __shfl_xor_sync(0xffffffffu, mx1, 2));

    float sum0 = 0.f, sum1 = 0.f;
#pragma unroll
    for (int nt = 0; nt < 16; nt++) {
        float p0 = __expf(sacc[nt][0] - mx0);
        float p1 = __expf(sacc[nt][1] - mx0);
        float p2 = __expf(sacc[nt][2] - mx1);
        float p3 = __expf(sacc[nt][3] - mx1);
        sum0 += p0 + p1;
        sum1 += p2 + p3;
        int c = nt * 8 + 2 * tig;
        Ps[rowL * APS + c]     = to_tf32(p0);
        Ps[rowL * APS + c + 1] = to_tf32(p1);
        Ps[rowH * APS + c]     = to_tf32(p2);
        Ps[rowH * APS + c + 1] = to_tf32(p3);
    }
    sum0 += __shfl_xor_sync(0xffffffffu, sum0, 1);
    sum0 += __shfl_xor_sync(0xffffffffu, sum0, 2);
    sum1 += __shfl_xor_sync(0xffffffffu, sum1, 1);
    sum1 += __shfl_xor_sync(0xffffffffu, sum1, 2);
    float inv0 = 1.f / sum0, inv1 = 1.f / sum1;
    __syncwarp();

    float oacc[8][4];
#pragma unroll
    for (int nt = 0; nt < 8; nt++) {
        oacc[nt][0] = 0.f; oacc[nt][1] = 0.f;
        oacc[nt][2] = 0.f; oacc[nt][3] = 0.f;
    }
#pragma unroll
    for (int kt = 0; kt < 16; kt++) {
        float pa[4];
        int k = kt * 8 + tig;
        pa[0] = Ps[rowL * APS + k];
        pa[1] = Ps[rowH * APS + k];
        pa[2] = Ps[rowL * APS + k + 4];
        pa[3] = Ps[rowH * APS + k + 4];
#pragma unroll
        for (int nt = 0; nt < 8; nt++) {
            float bf[2];
            bf[0] = Vs[(kt * 8 + tig) * AQS + nt * 8 + g];
            bf[1] = Vs[(kt * 8 + tig + 4) * AQS + nt * 8 + g];
            mma_tf32(oacc[nt], pa, bf);
        }
    }

    float* oL = o + ((long)(b * NN + rowL)) * INNER + h * DH;
    float* oH = o + ((long)(b * NN + rowH)) * INNER + h * DH;
#pragma unroll
    for (int nt = 0; nt < 8; nt++) {
        int c = nt * 8 + 2 * tig;
        float2 w0, w1;
        w0.x = oacc[nt][0] * inv0; w0.y = oacc[nt][1] * inv0;
        w1.x = oacc[nt][2] * inv1; w1.y = oacc[nt][3] * inv1;
        *(float2*)&oL[c] = w0;
        *(float2*)&oH[c] = w1;
    }
}

// ---------------------------------------------------------------------------
// Head: mean-pool over N, LayerNorm, dot with Wf
// ---------------------------------------------------------------------------
__global__ void head_kernel(const float* __restrict__ x, const float* __restrict__ g,
                            const float* __restrict__ be, const float* __restrict__ Wf,
                            const float* __restrict__ bf, float* __restrict__ out)
{
    __shared__ float pool[DLAT];
    int b = blockIdx.x;
    int t = threadIdx.x;     // 128 threads
    if (t < DLAT) {
        float s = 0.f;
        const float* xb = x + (long)b * NN * DLAT + t;
        for (int n = 0; n < NN; n++) s += xb[n * DLAT];
        pool[t] = s * (1.f / NN);
    }
    __syncthreads();
    if (t < 32) {
        float v0 = pool[t], v1 = pool[t + 32];
        float v2 = (t + 64 < DLAT) ? pool[t + 64] : 0.f;
        float s = v0 + v1 + v2;
#pragma unroll
        for (int o = 16; o; o >>= 1) s += __shfl_xor_sync(0xffffffffu, s, o);
        float mean = s * (1.f / DLAT);
        float d0 = v0 - mean, d1 = v1 - mean;
        float d2 = (t + 64 < DLAT) ? (v2 - mean) : 0.f;
        float vs = d0 * d0 + d1 * d1 + d2 * d2;
#pragma unroll
        for (int o = 16; o; o >>= 1) vs += __shfl_xor_sync(0xffffffffu, vs, o);
        float inv = rsqrtf(vs * (1.f / DLAT) + 1e-5f);
        float dot = (d0 * inv * g[t] + be[t]) * Wf[t]
                  + (d1 * inv * g[t + 32] + be[t + 32]) * Wf[t + 32];
        if (t + 64 < DLAT)
            dot += (d2 * inv * g[t + 64] + be[t + 64]) * Wf[t + 64];
#pragma unroll
        for (int o = 16; o; o >>= 1) dot += __shfl_xor_sync(0xffffffffu, dot, o);
        if (t == 0) out[b] = dot + bf[0];
    }
}

// ---------------------------------------------------------------------------
// Launch
// ---------------------------------------------------------------------------
extern "C" void kernel_launch(void* const* d_in, const int* in_sizes, int n_in,
                              void* d_out, int out_size)
{
    const int*   spatial_pos = (const int*)d_in[0];
    const int*   edge_input  = (const int*)d_in[1];
    const int*   x_nodes     = (const int*)d_in[2];
    const int*   indeg       = (const int*)d_in[3];
    const int*   outdeg      = (const int*)d_in[4];
    const float* atom_emb    = (const float*)d_in[5];
    const float* indeg_emb   = (const float*)d_in[6];
    const float* outdeg_emb  = (const float*)d_in[7];
    const float* edge_emb    = (const float*)d_in[8];
    const float* edge_dis_w  = (const float*)d_in[9];
    const float* spatial_emb = (const float*)d_in[10];
    const float* ln1_g = (const float*)d_in[11];
    const float* ln1_b = (const float*)d_in[12];
    const float* Wq    = (const float*)d_in[13];
    const float* Wkv   = (const float*)d_in[14];
    const float* Wo    = (const float*)d_in[15];
    const float* bo    = (const float*)d_in[16];
    const float* ln2_g = (const float*)d_in[17];
    const float* ln2_b = (const float*)d_in[18];
    const float* W1    = (const float*)d_in[19];
    const float* b1    = (const float*)d_in[20];
    const float* W2    = (const float*)d_in[21];
    const float* b2    = (const float*)d_in[22];
    const float* lnf_g = (const float*)d_in[23];
    const float* lnf_b = (const float*)d_in[24];
    const float* Wf    = (const float*)d_in[25];
    const float* bf    = (const float*)d_in[26];
    float* out = (float*)d_out;

    float *gx, *gqkv, *go, *gf, *gb;
    cudaGetSymbolAddress((void**)&gx,   g_x);
    cudaGetSymbolAddress((void**)&gqkv, g_qkv);
    cudaGetSymbolAddress((void**)&go,   g_o);
    cudaGetSymbolAddress((void**)&gf,   g_f);
    cudaGetSymbolAddress((void**)&gb,   g_bias);

    cudaFuncSetAttribute(attn_kernel,
                         cudaFuncAttributeMaxDynamicSharedMemorySize, ATTN_SMEM);
    cudaFuncSetAttribute(panel_gemm<0>,
                         cudaFuncAttributeMaxDynamicSharedMemorySize, PANEL_SMEM);
    cudaFuncSetAttribute(panel_gemm<2>,
                         cudaFuncAttributeMaxDynamicSharedMemorySize, PANEL_SMEM);

    bias_kernel<<<BB * NN, 128>>>(spatial_pos, edge_input, edge_emb,
                                  edge_dis_w, spatial_emb, gb);
    embed_kernel<<<ROWS, DLAT>>>(x_nodes, indeg, outdeg,
                                 atom_emb, indeg_emb, outdeg_emb, gx);

    for (int l = 0; l < DEPTH; l++) {
        // QKV: LN1 fused, dual weight (Wq cols [0,512), Wkv cols [512,1536))
        panel_gemm<0><<<dim3(24, ROWS / 128), 256, PANEL_SMEM>>>(
            gx, ln1_g + l * DLAT, ln1_b + l * DLAT,
            Wq + (long)l * DLAT * INNER, Wkv + (long)l * DLAT * 2 * INNER,
            INNER, 2 * INNER, nullptr, gqkv, 3 * INNER);
        attn_kernel<<<BB * NH, 256, ATTN_SMEM>>>(gqkv, gb, go);
        mma_gemm<1><<<dim3(2, ROWS / GBM), 256>>>(
            go, Wo + (long)l * INNER * DLAT, bo + l * DLAT, gx,
            gx, ROWS, INNER, DLAT, DLAT, 0);
        // FF1: LN2 fused, gelu epilogue
        panel_gemm<2><<<dim3(3, ROWS / 128), 256, PANEL_SMEM>>>(
            gx, ln2_g + l * DLAT, ln2_b + l * DLAT,
            W1 + (long)l * DLAT * FFD, nullptr,
            FFD, 0, b1 + l * FFD, gf, FFD);
        mma_gemm<1><<<dim3(2, ROWS / GBM), 256>>>(
            gf, W2 + (long)l * FFD * DLAT, b2 + l * DLAT, gx,
            gx, ROWS, FFD, DLAT, DLAT, 0);
    }

    head_kernel<<<BB, 128>>>(gx, lnf_g, lnf_b, Wf, bf, out);
}

// round 7
// speedup vs baseline: 2.0390x; 1.0567x over previous
#include <cuda_runtime.h>
#include <math.h>

// Problem constants
#define BB 64
#define NN 128
#define DLAT 80
#define NH 8
#define DH 64
#define INNER 512
#define FFD 160
#define MHD 20
#define DEPTH 24
#define ROWS (BB * NN)   // 8192

// ---------------------------------------------------------------------------
// Scratch (device globals; no allocation allowed)
// ---------------------------------------------------------------------------
__device__ float g_x[ROWS * DLAT];          // residual stream
__device__ float g_qkv[ROWS * 3 * INNER];   // fused Q|K|V (row stride 1536)
__device__ float g_o[ROWS * INNER];         // attention output
__device__ float g_f[ROWS * FFD];           // FF hidden
__device__ float g_bias[BB * NN * NN];      // graph attention bias

// ---------------------------------------------------------------------------
// tf32 helpers
// ---------------------------------------------------------------------------
__device__ __forceinline__ float to_tf32(float x)
{
    float r;
    asm("cvt.rna.tf32.f32 %0, %1;" : "=f"(r) : "f"(x));
    return r;
}

__device__ __forceinline__ void mma_tf32(float* c, const float* a, const float* b)
{
    asm volatile(
        "mma.sync.aligned.m16n8k8.row.col.f32.tf32.tf32.f32 "
        "{%0,%1,%2,%3}, {%4,%5,%6,%7}, {%8,%9}, {%0,%1,%2,%3};"
        : "+f"(c[0]), "+f"(c[1]), "+f"(c[2]), "+f"(c[3])
        : "r"(__float_as_uint(a[0])), "r"(__float_as_uint(a[1])),
          "r"(__float_as_uint(a[2])), "r"(__float_as_uint(a[3])),
          "r"(__float_as_uint(b[0])), "r"(__float_as_uint(b[1])));
}

// ---------------------------------------------------------------------------
// Graph bias
// ---------------------------------------------------------------------------
__global__ void bias_kernel(const int* __restrict__ spatial_pos,
                            const int* __restrict__ edge_input,
                            const float* __restrict__ edge_emb,
                            const float* __restrict__ edge_dis_w,
                            const float* __restrict__ spatial_emb,
                            float* __restrict__ bias)
{
    __shared__ float s_edge[64];
    __shared__ float s_w[MHD];
    __shared__ float s_sp[40];
    int t = threadIdx.x;               // 128 threads
    if (t < 64) s_edge[t] = edge_emb[t];
    if (t < MHD) s_w[t] = edge_dis_w[t];
    if (t >= 64 && t < 104) s_sp[t - 64] = spatial_emb[t - 64];
    __syncthreads();

    long bi = blockIdx.x;              // b*N + i
    int j = t;
    const int* ei = edge_input + (bi * NN + j) * (MHD * 3);
    float acc = 0.f;
#pragma unroll
    for (int hh = 0; hh < MHD; hh++) {
        float e = (s_edge[ei[hh * 3 + 0]] + s_edge[ei[hh * 3 + 1]] +
                   s_edge[ei[hh * 3 + 2]]) * (1.f / 3.f);
        acc += e * s_w[hh];
    }
    int sp0 = spatial_pos[bi * NN + j];
    int sp = (sp0 == 0) ? 1 : sp0;
    sp = (sp > 1) ? sp - 1 : sp;
    sp = min(sp, MHD);
    bias[bi * NN + j] = acc / (float)sp + s_sp[sp0];
}

// ---------------------------------------------------------------------------
// Node embedding
// ---------------------------------------------------------------------------
__global__ void embed_kernel(const int* __restrict__ x_nodes,
                             const int* __restrict__ indeg,
                             const int* __restrict__ outdeg,
                             const float* __restrict__ atom_emb,
                             const float* __restrict__ indeg_emb,
                             const float* __restrict__ outdeg_emb,
                             float* __restrict__ x)
{
    int r = blockIdx.x;      // 8192 rows
    int d = threadIdx.x;     // 80
    int a = x_nodes[r], i = indeg[r], o = outdeg[r];
    x[(long)r * DLAT + d] = atom_emb[a * DLAT + d] + indeg_emb[i * DLAT + d]
                          + outdeg_emb[o * DLAT + d];
}

// ---------------------------------------------------------------------------
// Panel GEMM with fused LayerNorm (K = DLAT = 80 only).
//   EPI 0: plain store     EPI 2: gelu_exact(acc + bias[n])
// ---------------------------------------------------------------------------
#define PAST 84
#define PANEL_SMEM ((128 + 64) * PAST * 4)   // 64512 bytes

template <int EPI>
__global__ void __launch_bounds__(256) panel_gemm(
    const float* __restrict__ X,
    const float* __restrict__ lng, const float* __restrict__ lnb,
    const float* __restrict__ Wa, const float* __restrict__ Wb,
    int NcA, int NcB,
    const float* __restrict__ bias,
    float* __restrict__ C, int ldc)
{
    extern __shared__ float smp[];
    float* As = smp;                // [128][84]
    float* Bs = smp + 128 * PAST;   // [64][84]

    int bm = blockIdx.y * 128;
    int n_glob = blockIdx.x * 64;
    const float* W; int Wn; int wcol;
    if (n_glob < NcA) { W = Wa; Wn = NcA; wcol = n_glob; }
    else             { W = Wb; Wn = NcB; wcol = n_glob - NcA; }
    int NcTot = NcA + NcB;

    int t = threadIdx.x;

    {   // A panel: load 128x80, fused LayerNorm, tf32 store
        int r = t >> 1, half = t & 1;
        const float* ar = X + (long)(bm + r) * DLAT + half * 40;
        float* ad = As + r * PAST + half * 40;
        float s = 0.f;
#pragma unroll
        for (int i = 0; i < 40; i += 4) {
            float4 a4 = *(const float4*)(ar + i);
            *(float4*)(ad + i) = a4;
            s += (a4.x + a4.y) + (a4.z + a4.w);
        }
        s += __shfl_xor_sync(0xffffffffu, s, 1);
        float mean = s * (1.f / DLAT);
        float vs = 0.f;
#pragma unroll
        for (int i = 0; i < 40; i++) { float d = ad[i] - mean; vs += d * d; }
        vs += __shfl_xor_sync(0xffffffffu, vs, 1);
        float inv = rsqrtf(vs * (1.f / DLAT) + 1e-5f);
        const float* gg = lng + half * 40;
        const float* bb = lnb + half * 40;
#pragma unroll
        for (int i = 0; i < 40; i++)
            ad[i] = to_tf32((ad[i] - mean) * inv * gg[i] + bb[i]);
    }

    {   // B panel: transpose-stage W[k][wcol+n] -> Bs[n][k] (tf32)
        int kr = t >> 4;          // 0..15
        int n0 = (t & 15) * 4;    // 0..60
#pragma unroll
        for (int kb = 0; kb < DLAT; kb += 16) {
            int k = kb + kr;
            float4 w4 = make_float4(0.f, 0.f, 0.f, 0.f);
            if (wcol + n0 < Wn) {
                const float* wp = W + (long)k * Wn + wcol + n0;
                if (wcol + n0 + 3 < Wn) {
                    w4 = *(const float4*)wp;
                } else {
                    w4.x = wp[0];
                    if (wcol + n0 + 1 < Wn) w4.y = wp[1];
                    if (wcol + n0 + 2 < Wn) w4.z = wp[2];
                }
            }
            Bs[(n0 + 0) * PAST + k] = to_tf32(w4.x);
            Bs[(n0 + 1) * PAST + k] = to_tf32(w4.y);
            Bs[(n0 + 2) * PAST + k] = to_tf32(w4.z);
            Bs[(n0 + 3) * PAST + k] = to_tf32(w4.w);
        }
    }
    __syncthreads();

    int warp = t >> 5, lane = t & 31;
    int g = lane >> 2, tig = lane & 3;
    int warpM = warp >> 1, warpN = warp & 1;

    float acc[2][4][4] = {};

#pragma unroll
    for (int kt = 0; kt < 10; kt++) {
        int kk = kt * 8;
        float af[2][4];
#pragma unroll
        for (int mt = 0; mt < 2; mt++) {
            int r = warpM * 32 + mt * 16;
            af[mt][0] = As[(r + g) * PAST + kk + tig];
            af[mt][1] = As[(r + g + 8) * PAST + kk + tig];
            af[mt][2] = As[(r + g) * PAST + kk + tig + 4];
            af[mt][3] = As[(r + g + 8) * PAST + kk + tig + 4];
        }
#pragma unroll
        for (int nt = 0; nt < 4; nt++) {
            float bf[2];
            int n = warpN * 32 + nt * 8 + g;
            bf[0] = Bs[n * PAST + kk + tig];
            bf[1] = Bs[n * PAST + kk + tig + 4];
#pragma unroll
            for (int mt = 0; mt < 2; mt++)
                mma_tf32(acc[mt][nt], af[mt], bf);
        }
    }

#pragma unroll
    for (int mt = 0; mt < 2; mt++) {
        long rL = bm + warpM * 32 + mt * 16 + g;
        long rH = rL + 8;
#pragma unroll
        for (int nt = 0; nt < 4; nt++) {
            int n = n_glob + warpN * 32 + nt * 8 + 2 * tig;
            if (n >= NcTot) continue;
            float v0 = acc[mt][nt][0], v1 = acc[mt][nt][1];
            float v2 = acc[mt][nt][2], v3 = acc[mt][nt][3];
            if (EPI == 2) {
                float b0 = bias[n], b1 = bias[n + 1];
                v0 += b0; v1 += b1; v2 += b0; v3 += b1;
                v0 = 0.5f * v0 * (1.f + erff(v0 * 0.70710678118654752f));
                v1 = 0.5f * v1 * (1.f + erff(v1 * 0.70710678118654752f));
                v2 = 0.5f * v2 * (1.f + erff(v2 * 0.70710678118654752f));
                v3 = 0.5f * v3 * (1.f + erff(v3 * 0.70710678118654752f));
            }
            float2 w0, w1;
            w0.x = v0; w0.y = v1;
            w1.x = v2; w1.y = v3;
            *(float2*)&C[rL * ldc + n] = w0;
            *(float2*)&C[rH * ldc + n] = w1;
        }
    }
}

// ---------------------------------------------------------------------------
// Chunked tf32 GEMM (K-loop) for Wo (K=512) and FF2 (K=160).
//   EPI 1: +bias[n]+res[m,n]
// ---------------------------------------------------------------------------
#define GBM 128
#define GBN 64
#define GBK 16
#define GAS 20
#define GBS 20

template <int EPI>
__global__ void __launch_bounds__(256) mma_gemm(
    const float* __restrict__ A, const float* __restrict__ W,
    const float* __restrict__ bias, const float* __restrict__ res,
    float* __restrict__ C, int M, int K, int Nc, int ldc, int coff)
{
    __shared__ float As[GBM * GAS];
    __shared__ float Bs[GBN * GBS];
    int bm = blockIdx.y * GBM;
    int bn = blockIdx.x * GBN;
    int tid = threadIdx.x;
    int warp = tid >> 5, lane = tid & 31;
    int g = lane >> 2, tig = lane & 3;
    int warpM = warp >> 1, warpN = warp & 1;

    float acc[2][4][4] = {};

    for (int k0 = 0; k0 < K; k0 += GBK) {
        {
            int m = tid >> 1;
            int kq = (tid & 1) * 8;
            const float* ap = A + (long)(bm + m) * K + k0 + kq;
            float4 a0 = *(const float4*)ap;
            float4 a1 = *(const float4*)(ap + 4);
            float* ad = As + m * GAS + kq;
            ad[0] = to_tf32(a0.x); ad[1] = to_tf32(a0.y);
            ad[2] = to_tf32(a0.z); ad[3] = to_tf32(a0.w);
            ad[4] = to_tf32(a1.x); ad[5] = to_tf32(a1.y);
            ad[6] = to_tf32(a1.z); ad[7] = to_tf32(a1.w);
        }
        {
            int kr = tid >> 4;
            int n0 = (tid & 15) * 4;
            const float* wp = W + (long)(k0 + kr) * Nc + bn + n0;
            float4 w4 = make_float4(0.f, 0.f, 0.f, 0.f);
            if (bn + n0 + 3 < Nc) {
                w4 = *(const float4*)wp;
            } else if (bn + n0 < Nc) {
                w4.x = wp[0];
                if (bn + n0 + 1 < Nc) w4.y = wp[1];
                if (bn + n0 + 2 < Nc) w4.z = wp[2];
            }
            Bs[(n0 + 0) * GBS + kr] = to_tf32(w4.x);
            Bs[(n0 + 1) * GBS + kr] = to_tf32(w4.y);
            Bs[(n0 + 2) * GBS + kr] = to_tf32(w4.z);
            Bs[(n0 + 3) * GBS + kr] = to_tf32(w4.w);
        }
        __syncthreads();
#pragma unroll
        for (int kt = 0; kt < 2; kt++) {
            int kk = kt * 8;
            float af[2][4];
#pragma unroll
            for (int mt = 0; mt < 2; mt++) {
                int r = warpM * 32 + mt * 16;
                af[mt][0] = As[(r + g) * GAS + kk + tig];
                af[mt][1] = As[(r + g + 8) * GAS + kk + tig];
                af[mt][2] = As[(r + g) * GAS + kk + tig + 4];
                af[mt][3] = As[(r + g + 8) * GAS + kk + tig + 4];
            }
#pragma unroll
            for (int nt = 0; nt < 4; nt++) {
                float bf[2];
                int n = warpN * 32 + nt * 8 + g;
                bf[0] = Bs[n * GBS + kk + tig];
                bf[1] = Bs[n * GBS + kk + tig + 4];
#pragma unroll
                for (int mt = 0; mt < 2; mt++)
                    mma_tf32(acc[mt][nt], af[mt], bf);
            }
        }
        __syncthreads();
    }

#pragma unroll
    for (int mt = 0; mt < 2; mt++) {
        long rL = bm + warpM * 32 + mt * 16 + g;
        long rH = rL + 8;
#pragma unroll
        for (int nt = 0; nt < 4; nt++) {
            int n = bn + warpN * 32 + nt * 8 + 2 * tig;
            if (n >= Nc) continue;
            float v0 = acc[mt][nt][0], v1 = acc[mt][nt][1];
            float v2 = acc[mt][nt][2], v3 = acc[mt][nt][3];
            if (EPI == 1) {
                float b0 = bias[n], b1 = bias[n + 1];
                const float* rL_p = res + rL * Nc + n;
                const float* rH_p = res + rH * Nc + n;
                v0 += b0 + rL_p[0]; v1 += b1 + rL_p[1];
                v2 += b0 + rH_p[0]; v3 += b1 + rH_p[1];
            }
            float2 w0, w1;
            w0.x = v0; w0.y = v1;
            w1.x = v2; w1.y = v3;
            *(float2*)&C[rL * ldc + coff + n] = w0;
            *(float2*)&C[rH * ldc + coff + n] = w1;
        }
    }
}

// ---------------------------------------------------------------------------
// Flash-style tensor-core attention: block=(b,h), 8 warps, 2 j-chunks of 64
// with online softmax. Smem: K/V chunk [64][68] each + P/Q strip [128][68]
// = 68 KB -> 2 blocks/SM. Regs capped at 128 via launch_bounds(256,2).
// ---------------------------------------------------------------------------
#define AKS 68
#define ATTN_SMEM ((2 * 64 * AKS + NN * AKS) * 4)   // 69632 bytes

__global__ void __launch_bounds__(256, 2) attn_kernel(
    const float* __restrict__ qkv, const float* __restrict__ bias,
    float* __restrict__ o)
{
    extern __shared__ float sm[];
    float* Ks = sm;                   // [64][68] chunk
    float* Vs = sm + 64 * AKS;        // [64][68] chunk
    float* Ps = sm + 2 * 64 * AKS;    // [128][68]: Q staging, then P strips

    int bh = blockIdx.x;
    int b = bh >> 3, h = bh & 7;
    int t = threadIdx.x;

    // Stage Q into Ps (coalesced), tf32
    {
        int r = t >> 1, half = t & 1;
        const float* qr = qkv + ((long)(b * NN + r)) * 1536 + h * DH + half * 32;
        float* qd = Ps + r * AKS + half * 32;
#pragma unroll
        for (int i = 0; i < 32; i += 4) {
            float4 q4 = *(const float4*)(qr + i);
            qd[i]     = to_tf32(q4.x); qd[i + 1] = to_tf32(q4.y);
            qd[i + 2] = to_tf32(q4.z); qd[i + 3] = to_tf32(q4.w);
        }
    }
    __syncthreads();

    int warp = t >> 5, lane = t & 31;
    int g = lane >> 2, tig = lane & 3;
    int m0 = warp * 16;
    int rowL = m0 + g, rowH = m0 + g + 8;

    // Q fragments (persistent)
    float qa[8][4];
#pragma unroll
    for (int kt = 0; kt < 8; kt++) {
        int k = kt * 8 + tig;
        qa[kt][0] = Ps[rowL * AKS + k];
        qa[kt][1] = Ps[rowH * AKS + k];
        qa[kt][2] = Ps[rowL * AKS + k + 4];
        qa[kt][3] = Ps[rowH * AKS + k + 4];
    }

    float mr0 = -1e30f, mr1 = -1e30f, sum0 = 0.f, sum1 = 0.f;
    float oacc[8][4] = {};

#pragma unroll
    for (int jc = 0; jc < 2; jc++) {
        int j0 = jc * 64;
        __syncthreads();   // K/V reuse + Q/P strip hazard fence
        {   // load K,V chunk rows j0..j0+63 (coalesced quarters), tf32
            int r2 = t >> 2;
            int q4o = (t & 3) * 16;
            const float* kr = qkv + ((long)(b * NN + j0 + r2)) * 1536 + 512
                              + h * DH + q4o;
            const float* vr = kr + 512;
            float* kd = Ks + r2 * AKS + q4o;
            float* vd = Vs + r2 * AKS + q4o;
#pragma unroll
            for (int i = 0; i < 16; i += 4) {
                float4 k4 = *(const float4*)(kr + i);
                float4 v4 = *(const float4*)(vr + i);
                kd[i]     = to_tf32(k4.x); kd[i + 1] = to_tf32(k4.y);
                kd[i + 2] = to_tf32(k4.z); kd[i + 3] = to_tf32(k4.w);
                vd[i]     = to_tf32(v4.x); vd[i + 1] = to_tf32(v4.y);
                vd[i + 2] = to_tf32(v4.z); vd[i + 3] = to_tf32(v4.w);
            }
        }
        __syncthreads();

        // S chunk = Q @ K_chunk^T
        float sacc[8][4] = {};
#pragma unroll
        for (int kt = 0; kt < 8; kt++) {
#pragma unroll
            for (int nt = 0; nt < 8; nt++) {
                float bf[2];
                const float* kp = Ks + (nt * 8 + g) * AKS + kt * 8 + tig;
                bf[0] = kp[0];
                bf[1] = kp[4];
                mma_tf32(sacc[nt], qa[kt], bf);
            }
        }

        // scale + bias + chunk max
        const float* bL = bias + ((long)b * NN + rowL) * NN + j0 + 2 * tig;
        const float* bH = bias + ((long)b * NN + rowH) * NN + j0 + 2 * tig;
        float cm0 = -1e30f, cm1 = -1e30f;
#pragma unroll
        for (int nt = 0; nt < 8; nt++) {
            float2 b0 = *(const float2*)(bL + nt * 8);
            float2 b1 = *(const float2*)(bH + nt * 8);
            sacc[nt][0] = sacc[nt][0] * 0.125f + b0.x;
            sacc[nt][1] = sacc[nt][1] * 0.125f + b0.y;
            sacc[nt][2] = sacc[nt][2] * 0.125f + b1.x;
            sacc[nt][3] = sacc[nt][3] * 0.125f + b1.y;
            cm0 = fmaxf(cm0, fmaxf(sacc[nt][0], sacc[nt][1]));
            cm1 = fmaxf(cm1, fmaxf(sacc[nt][2], sacc[nt][3]));
        }
        cm0 = fmaxf(cm0, __shfl_xor_sync(0xffffffffu, cm0, 1));
        cm0 = fmaxf(cm0, __shfl_xor_sync(0xffffffffu, cm0, 2));
        cm1 = fmaxf(cm1, __shfl_xor_sync(0xffffffffu, cm1, 1));
        cm1 = fmaxf(cm1, __shfl_xor_sync(0xffffffffu, cm1, 2));

        float mn0 = fmaxf(mr0, cm0), mn1 = fmaxf(mr1, cm1);
        float c0 = __expf(mr0 - mn0), c1 = __expf(mr1 - mn1);
        mr0 = mn0; mr1 = mn1;
        sum0 *= c0; sum1 *= c1;
#pragma unroll
        for (int nt = 0; nt < 8; nt++) {
            oacc[nt][0] *= c0; oacc[nt][1] *= c0;
            oacc[nt][2] *= c1; oacc[nt][3] *= c1;
        }

        // exp + P store (warp-private rows)
#pragma unroll
        for (int nt = 0; nt < 8; nt++) {
            float p0 = __expf(sacc[nt][0] - mr0);
            float p1 = __expf(sacc[nt][1] - mr0);
            float p2 = __expf(sacc[nt][2] - mr1);
            float p3 = __expf(sacc[nt][3] - mr1);
            sum0 += p0 + p1;
            sum1 += p2 + p3;
            int c = nt * 8 + 2 * tig;
            Ps[rowL * AKS + c]     = to_tf32(p0);
            Ps[rowL * AKS + c + 1] = to_tf32(p1);
            Ps[rowH * AKS + c]     = to_tf32(p2);
            Ps[rowH * AKS + c + 1] = to_tf32(p3);
        }
        __syncwarp();

        // O += P_chunk @ V_chunk
#pragma unroll
        for (int kt = 0; kt < 8; kt++) {
            float pa[4];
            int k = kt * 8 + tig;
            pa[0] = Ps[rowL * AKS + k];
            pa[1] = Ps[rowH * AKS + k];
            pa[2] = Ps[rowL * AKS + k + 4];
            pa[3] = Ps[rowH * AKS + k + 4];
#pragma unroll
            for (int nt = 0; nt < 8; nt++) {
                float bf[2];
                bf[0] = Vs[(kt * 8 + tig) * AKS + nt * 8 + g];
                bf[1] = Vs[(kt * 8 + tig + 4) * AKS + nt * 8 + g];
                mma_tf32(oacc[nt], pa, bf);
            }
        }
    }

    // Cross-lane reduction of row sums (THE R5 BUG: this was missing)
    sum0 += __shfl_xor_sync(0xffffffffu, sum0, 1);
    sum0 += __shfl_xor_sync(0xffffffffu, sum0, 2);
    sum1 += __shfl_xor_sync(0xffffffffu, sum1, 1);
    sum1 += __shfl_xor_sync(0xffffffffu, sum1, 2);

    float inv0 = 1.f / sum0, inv1 = 1.f / sum1;
    float* oL = o + ((long)(b * NN + rowL)) * INNER + h * DH;
    float* oH = o + ((long)(b * NN + rowH)) * INNER + h * DH;
#pragma unroll
    for (int nt = 0; nt < 8; nt++) {
        int c = nt * 8 + 2 * tig;
        float2 w0, w1;
        w0.x = oacc[nt][0] * inv0; w0.y = oacc[nt][1] * inv0;
        w1.x = oacc[nt][2] * inv1; w1.y = oacc[nt][3] * inv1;
        *(float2*)&oL[c] = w0;
        *(float2*)&oH[c] = w1;
    }
}

// ---------------------------------------------------------------------------
// Head: mean-pool over N, LayerNorm, dot with Wf
// ---------------------------------------------------------------------------
__global__ void head_kernel(const float* __restrict__ x, const float* __restrict__ g,
                            const float* __restrict__ be, const float* __restrict__ Wf,
                            const float* __restrict__ bf, float* __restrict__ out)
{
    __shared__ float pool[DLAT];
    int b = blockIdx.x;
    int t = threadIdx.x;     // 128 threads
    if (t < DLAT) {
        float s = 0.f;
        const float* xb = x + (long)b * NN * DLAT + t;
        for (int n = 0; n < NN; n++) s += xb[n * DLAT];
        pool[t] = s * (1.f / NN);
    }
    __syncthreads();
    if (t < 32) {
        float v0 = pool[t], v1 = pool[t + 32];
        float v2 = (t + 64 < DLAT) ? pool[t + 64] : 0.f;
        float s = v0 + v1 + v2;
#pragma unroll
        for (int o = 16; o; o >>= 1) s += __shfl_xor_sync(0xffffffffu, s, o);
        float mean = s * (1.f / DLAT);
        float d0 = v0 - mean, d1 = v1 - mean;
        float d2 = (t + 64 < DLAT) ? (v2 - mean) : 0.f;
        float vs = d0 * d0 + d1 * d1 + d2 * d2;
#pragma unroll
        for (int o = 16; o; o >>= 1) vs += __shfl_xor_sync(0xffffffffu, vs, o);
        float inv = rsqrtf(vs * (1.f / DLAT) + 1e-5f);
        float dot = (d0 * inv * g[t] + be[t]) * Wf[t]
                  + (d1 * inv * g[t + 32] + be[t + 32]) * Wf[t + 32];
        if (t + 64 < DLAT)
            dot += (d2 * inv * g[t + 64] + be[t + 64]) * Wf[t + 64];
#pragma unroll
        for (int o = 16; o; o >>= 1) dot += __shfl_xor_sync(0xffffffffu, dot, o);
        if (t == 0) out[b] = dot + bf[0];
    }
}

// ---------------------------------------------------------------------------
// Launch
// ---------------------------------------------------------------------------
extern "C" void kernel_launch(void* const* d_in, const int* in_sizes, int n_in,
                              void* d_out, int out_size)
{
    const int*   spatial_pos = (const int*)d_in[0];
    const int*   edge_input  = (const int*)d_in[1];
    const int*   x_nodes     = (const int*)d_in[2];
    const int*   indeg       = (const int*)d_in[3];
    const int*   outdeg      = (const int*)d_in[4];
    const float* atom_emb    = (const float*)d_in[5];
    const float* indeg_emb   = (const float*)d_in[6];
    const float* outdeg_emb  = (const float*)d_in[7];
    const float* edge_emb    = (const float*)d_in[8];
    const float* edge_dis_w  = (const float*)d_in[9];
    const float* spatial_emb = (const float*)d_in[10];
    const float* ln1_g = (const float*)d_in[11];
    const float* ln1_b = (const float*)d_in[12];
    const float* Wq    = (const float*)d_in[13];
    const float* Wkv   = (const float*)d_in[14];
    const float* Wo    = (const float*)d_in[15];
    const float* bo    = (const float*)d_in[16];
    const float* ln2_g = (const float*)d_in[17];
    const float* ln2_b = (const float*)d_in[18];
    const float* W1    = (const float*)d_in[19];
    const float* b1    = (const float*)d_in[20];
    const float* W2    = (const float*)d_in[21];
    const float* b2    = (const float*)d_in[22];
    const float* lnf_g = (const float*)d_in[23];
    const float* lnf_b = (const float*)d_in[24];
    const float* Wf    = (const float*)d_in[25];
    const float* bf    = (const float*)d_in[26];
    float* out = (float*)d_out;

    float *gx, *gqkv, *go, *gf, *gb;
    cudaGetSymbolAddress((void**)&gx,   g_x);
    cudaGetSymbolAddress((void**)&gqkv, g_qkv);
    cudaGetSymbolAddress((void**)&go,   g_o);
    cudaGetSymbolAddress((void**)&gf,   g_f);
    cudaGetSymbolAddress((void**)&gb,   g_bias);

    cudaFuncSetAttribute(attn_kernel,
                         cudaFuncAttributeMaxDynamicSharedMemorySize, ATTN_SMEM);
    cudaFuncSetAttribute(panel_gemm<0>,
                         cudaFuncAttributeMaxDynamicSharedMemorySize, PANEL_SMEM);
    cudaFuncSetAttribute(panel_gemm<2>,
                         cudaFuncAttributeMaxDynamicSharedMemorySize, PANEL_SMEM);

    bias_kernel<<<BB * NN, 128>>>(spatial_pos, edge_input, edge_emb,
                                  edge_dis_w, spatial_emb, gb);
    embed_kernel<<<ROWS, DLAT>>>(x_nodes, indeg, outdeg,
                                 atom_emb, indeg_emb, outdeg_emb, gx);

    for (int l = 0; l < DEPTH; l++) {
        panel_gemm<0><<<dim3(24, ROWS / 128), 256, PANEL_SMEM>>>(
            gx, ln1_g + l * DLAT, ln1_b + l * DLAT,
            Wq + (long)l * DLAT * INNER, Wkv + (long)l * DLAT * 2 * INNER,
            INNER, 2 * INNER, nullptr, gqkv, 3 * INNER);
        attn_kernel<<<BB * NH, 256, ATTN_SMEM>>>(gqkv, gb, go);
        mma_gemm<1><<<dim3(2, ROWS / GBM), 256>>>(
            go, Wo + (long)l * INNER * DLAT, bo + l * DLAT, gx,
            gx, ROWS, INNER, DLAT, DLAT, 0);
        panel_gemm<2><<<dim3(3, ROWS / 128), 256, PANEL_SMEM>>>(
            gx, ln2_g + l * DLAT, ln2_b + l * DLAT,
            W1 + (long)l * DLAT * FFD, nullptr,
            FFD, 0, b1 + l * FFD, gf, FFD);
        mma_gemm<1><<<dim3(2, ROWS / GBM), 256>>>(
            gf, W2 + (long)l * FFD * DLAT, b2 + l * DLAT, gx,
            gx, ROWS, FFD, DLAT, DLAT, 0);
    }

    head_kernel<<<BB, 128>>>(gx, lnf_g, lnf_b, Wf, bf, out);
}